// round 1
// baseline (speedup 1.0000x reference)
#include <cuda_runtime.h>

// ---------------------------------------------------------------------------
// Problem constants (MultiHeadAttentionLinear: B=2, S=1024, D=512, H=8,
// per-head dim = 512 because reshape(b,s,h,-1) on H*D features).
// ---------------------------------------------------------------------------
namespace cfg {
constexpr int BATCH = 2;
constexpr int SEQ   = 1024;
constexpr int DIM   = 512;      // per-head dim == input dim
constexpr int HEADS = 8;
constexpr int HB    = HEADS * BATCH;   // 16 attention batches
constexpr float NEGINF = -1e30f;
}

// ---------------------------------------------------------------------------
// Scratch (static __device__ arrays; dynamic allocation is forbidden)
// ---------------------------------------------------------------------------
__device__ float g_Q[(size_t)cfg::HB * cfg::SEQ * cfg::DIM];     // 32 MB (h,b,s,d)
__device__ float g_K[(size_t)cfg::HB * cfg::SEQ * cfg::DIM];     // 32 MB
__device__ float g_V[(size_t)cfg::HB * cfg::SEQ * cfg::DIM];     // 32 MB
__device__ float g_E[(size_t)cfg::HB * cfg::SEQ * cfg::SEQ];     // 64 MB (h,b,s,t)
__device__ float g_XP[(size_t)cfg::BATCH * cfg::SEQ * cfg::DIM]; // 4 MB  (b,s,d)
__device__ float g_maskAdd[cfg::SEQ];                            // 0 or -1e30

// ---------------------------------------------------------------------------
// Mask decode. The reference mask is boolean; the harness may hand it to us
// as uint8, int32 or float32. Detect from byte patterns using ONLY the first
// 1024 bytes (safe under every hypothesis), then read with the right stride.
//   float32 1.0f -> bytes {00,00,80,3F}: byte 0x3F at offset%4==3
//   int32   0/1 -> nonzero bytes only at offset%4==0
//   uint8   0/1 -> nonzero bytes at arbitrary offsets (95% ones)
// ---------------------------------------------------------------------------
__global__ void decode_mask_kernel(const unsigned char* __restrict__ mraw) {
    __shared__ int flags[2];   // [0]=looks float32, [1]=nonzero at misaligned byte
    const int t = threadIdx.x; // 1024 threads
    if (t < 2) flags[t] = 0;
    __syncthreads();
    const unsigned char bch = mraw[t];
    if (((t & 3) == 3) && bch == 0x3F) atomicOr(&flags[0], 1);
    if (((t & 3) != 0) && bch != 0)    atomicOr(&flags[1], 1);
    __syncthreads();
    bool valid;
    if (flags[0]) {            // float32
        valid = reinterpret_cast<const float*>(mraw)[t] != 0.0f;
    } else if (flags[1]) {     // uint8 / bool
        valid = (bch != 0);
    } else {                   // int32
        valid = reinterpret_cast<const int*>(mraw)[t] != 0;
    }
    g_maskAdd[t] = valid ? 0.0f : cfg::NEGINF;
}

// ---------------------------------------------------------------------------
// Generic fp32 tiled GEMM: C[z] = op(A[z]) * op(B[z]) (+ epilogue)
//   BM=BN=128, BK=8, 256 threads, 8x8 microtile per thread.
//   TA: A is K-major-transposed  (A[k*lda + m]),  else A[m*lda + k]
//   TB: B is transposed          (B[n*ldb + k]),  else B[k*ldb + n]
//   EPI 0: plain store            C[z*sC + m*ldc + n]
//   EPI 1: +bias, head relayout   (proj -> g_Q/g_K/g_V, (h,b,s,d))
//   EPI 2: +maskAdd[n], store     (energy)
//   EPI 3: gamma/xp blend, write final output layout (b,h,t,d)
// All dims are exact multiples of the tile sizes -> no bounds checks.
// ---------------------------------------------------------------------------
template<int TA, int TB, int EPI>
__global__ __launch_bounds__(256, 2)
void gemm_kernel(const float* __restrict__ A, const float* __restrict__ B,
                 float* __restrict__ C,
                 int K, int lda, int ldb, int ldc,
                 long long sA, long long sB, long long sC,
                 const float* __restrict__ aux)  // bias (EPI1) or gamma (EPI3)
{
    constexpr int BM = 128, BN = 128, BK = 8;
    __shared__ float As[BK][BM];
    __shared__ float Bs[BK][BN];

    const int bm  = blockIdx.y * BM;
    const int bn  = blockIdx.x * BN;
    const int z   = blockIdx.z;
    A += (size_t)z * sA;
    B += (size_t)z * sB;

    const int tid = threadIdx.x;
    const int ty  = tid >> 4;        // 0..15
    const int tx  = tid & 15;        // 0..15

    float acc[8][8];
#pragma unroll
    for (int i = 0; i < 8; i++)
#pragma unroll
        for (int j = 0; j < 8; j++) acc[i][j] = 0.0f;

    for (int k0 = 0; k0 < K; k0 += BK) {
        if constexpr (!TA) {
            const int r = tid >> 1;           // 0..127
            const int c = (tid & 1) * 4;      // 0 or 4
            float4 v = *reinterpret_cast<const float4*>(
                A + (size_t)(bm + r) * lda + k0 + c);
            As[c + 0][r] = v.x; As[c + 1][r] = v.y;
            As[c + 2][r] = v.z; As[c + 3][r] = v.w;
        } else {
            const int kk = tid >> 5;          // 0..7
            const int mm = (tid & 31) * 4;    // 0..124
            *reinterpret_cast<float4*>(&As[kk][mm]) =
                *reinterpret_cast<const float4*>(A + (size_t)(k0 + kk) * lda + bm + mm);
        }
        if constexpr (!TB) {
            const int kk = tid >> 5;
            const int nn = (tid & 31) * 4;
            *reinterpret_cast<float4*>(&Bs[kk][nn]) =
                *reinterpret_cast<const float4*>(B + (size_t)(k0 + kk) * ldb + bn + nn);
        } else {
            const int r = tid >> 1;
            const int c = (tid & 1) * 4;
            float4 v = *reinterpret_cast<const float4*>(
                B + (size_t)(bn + r) * ldb + k0 + c);
            Bs[c + 0][r] = v.x; Bs[c + 1][r] = v.y;
            Bs[c + 2][r] = v.z; Bs[c + 3][r] = v.w;
        }
        __syncthreads();

#pragma unroll
        for (int kk = 0; kk < BK; kk++) {
            float a[8], b[8];
#pragma unroll
            for (int i = 0; i < 8; i++) a[i] = As[kk][ty * 8 + i];
#pragma unroll
            for (int j = 0; j < 8; j++) b[j] = Bs[kk][tx * 8 + j];
#pragma unroll
            for (int i = 0; i < 8; i++)
#pragma unroll
                for (int j = 0; j < 8; j++)
                    acc[i][j] += a[i] * b[j];
        }
        __syncthreads();
    }

    // ---------------- epilogue ----------------
    const int colBase = bn + tx * 8;

    float g = 0.0f, inv_gp1 = 0.0f;
    int hh = 0, bb = 0;
    if constexpr (EPI == 3) {
        hh = z >> 1;          // batch order is (h*BATCH + b)
        bb = z & 1;
        g = aux[hh];
        inv_gp1 = 1.0f / (g + 1.0f);
    }

#pragma unroll
    for (int i = 0; i < 8; i++) {
        const int row = bm + ty * 8 + i;
        float v[8];
        if constexpr (EPI == 0) {
#pragma unroll
            for (int j = 0; j < 8; j++) v[j] = acc[i][j];
            float* dst = C + (size_t)z * sC + (size_t)row * ldc + colBase;
            *reinterpret_cast<float4*>(dst + 0) = make_float4(v[0], v[1], v[2], v[3]);
            *reinterpret_cast<float4*>(dst + 4) = make_float4(v[4], v[5], v[6], v[7]);
        } else if constexpr (EPI == 1) {
#pragma unroll
            for (int j = 0; j < 8; j++) v[j] = acc[i][j] + aux[colBase + j];
            const int h  = colBase >> 9;        // per-head dim = 512
            const int dd = colBase & 511;
            const int b  = row >> 10;           // S = 1024
            const int s  = row & 1023;
            float* dst = C + ((size_t)((h * cfg::BATCH + b) * cfg::SEQ + s)) * cfg::DIM + dd;
            *reinterpret_cast<float4*>(dst + 0) = make_float4(v[0], v[1], v[2], v[3]);
            *reinterpret_cast<float4*>(dst + 4) = make_float4(v[4], v[5], v[6], v[7]);
        } else if constexpr (EPI == 2) {
#pragma unroll
            for (int j = 0; j < 8; j++) v[j] = acc[i][j] + g_maskAdd[colBase + j];
            float* dst = C + (size_t)z * sC + (size_t)row * ldc + colBase;
            *reinterpret_cast<float4*>(dst + 0) = make_float4(v[0], v[1], v[2], v[3]);
            *reinterpret_cast<float4*>(dst + 4) = make_float4(v[4], v[5], v[6], v[7]);
        } else {  // EPI == 3: out = (gamma*acc + xp) / (gamma + 1), layout (b,h,t,d)
            const float* xpp = g_XP + ((size_t)(bb * cfg::SEQ + row)) * cfg::DIM + colBase;
            float4 x0 = *reinterpret_cast<const float4*>(xpp + 0);
            float4 x1 = *reinterpret_cast<const float4*>(xpp + 4);
            v[0] = (g * acc[i][0] + x0.x) * inv_gp1;
            v[1] = (g * acc[i][1] + x0.y) * inv_gp1;
            v[2] = (g * acc[i][2] + x0.z) * inv_gp1;
            v[3] = (g * acc[i][3] + x0.w) * inv_gp1;
            v[4] = (g * acc[i][4] + x1.x) * inv_gp1;
            v[5] = (g * acc[i][5] + x1.y) * inv_gp1;
            v[6] = (g * acc[i][6] + x1.z) * inv_gp1;
            v[7] = (g * acc[i][7] + x1.w) * inv_gp1;
            float* dst = C + ((size_t)((bb * cfg::HEADS + hh) * cfg::SEQ + row)) * cfg::DIM + colBase;
            *reinterpret_cast<float4*>(dst + 0) = make_float4(v[0], v[1], v[2], v[3]);
            *reinterpret_cast<float4*>(dst + 4) = make_float4(v[4], v[5], v[6], v[7]);
        }
    }
}

// ---------------------------------------------------------------------------
// Row softmax over the last axis of g_E (16384 rows of 1024 floats).
// One 256-thread block per row; masked entries carry -1e30 and underflow to 0.
// ---------------------------------------------------------------------------
__global__ void softmax_kernel(float* __restrict__ E) {
    const size_t row = blockIdx.x;
    float4* p = reinterpret_cast<float4*>(E + row * cfg::SEQ);
    const int tid = threadIdx.x;

    float4 v = p[tid];
    __shared__ float red[8];

    // max
    float m = fmaxf(fmaxf(v.x, v.y), fmaxf(v.z, v.w));
#pragma unroll
    for (int o = 16; o > 0; o >>= 1) m = fmaxf(m, __shfl_xor_sync(0xffffffffu, m, o));
    if ((tid & 31) == 0) red[tid >> 5] = m;
    __syncthreads();
    if (tid == 0) {
        float mm = red[0];
#pragma unroll
        for (int i = 1; i < 8; i++) mm = fmaxf(mm, red[i]);
        red[0] = mm;
    }
    __syncthreads();
    m = red[0];
    __syncthreads();   // before red[] is reused for the sum

    v.x = __expf(v.x - m);
    v.y = __expf(v.y - m);
    v.z = __expf(v.z - m);
    v.w = __expf(v.w - m);

    float s = v.x + v.y + v.z + v.w;
#pragma unroll
    for (int o = 16; o > 0; o >>= 1) s += __shfl_xor_sync(0xffffffffu, s, o);
    if ((tid & 31) == 0) red[tid >> 5] = s;
    __syncthreads();
    if (tid == 0) {
        float ss = red[0];
#pragma unroll
        for (int i = 1; i < 8; i++) ss += red[i];
        red[0] = ss;
    }
    __syncthreads();
    const float inv = 1.0f / red[0];

    v.x *= inv; v.y *= inv; v.z *= inv; v.w *= inv;
    p[tid] = v;
}

// ---------------------------------------------------------------------------
// Launcher
// ---------------------------------------------------------------------------
extern "C" void kernel_launch(void* const* d_in, const int* in_sizes, int n_in,
                              void* d_out, int out_size) {
    using namespace cfg;
    const float* x     = (const float*)d_in[0];   // (B,S,D)
    const float* y     = (const float*)d_in[1];   // (B,S,D)
    const float* Wq    = (const float*)d_in[2];   // (D, H*D)
    const float* bq    = (const float*)d_in[3];   // (H*D)
    const float* Wk    = (const float*)d_in[4];
    const float* bk    = (const float*)d_in[5];
    const float* Wv    = (const float*)d_in[6];
    const float* bv    = (const float*)d_in[7];
    const float* Wp    = (const float*)d_in[8];   // (D, D)
    const float* gamma = (const float*)d_in[9];   // (H)
    const unsigned char* mask = (const unsigned char*)d_in[10]; // (S) bool-ish
    float* out = (float*)d_out;                   // (B,H,S,D)

    float *pQ, *pK, *pV, *pE, *pXP;
    cudaGetSymbolAddress((void**)&pQ,  g_Q);
    cudaGetSymbolAddress((void**)&pK,  g_K);
    cudaGetSymbolAddress((void**)&pV,  g_V);
    cudaGetSymbolAddress((void**)&pE,  g_E);
    cudaGetSymbolAddress((void**)&pXP, g_XP);

    const long long sQKV = (long long)SEQ * DIM;   // per (h,b) matrix
    const long long sE   = (long long)SEQ * SEQ;

    decode_mask_kernel<<<1, 1024>>>(mask);

    // Projections: M=2048 (b,s), N=4096 (h,d), K=512; head-major relayout + bias
    dim3 blk(256);
    gemm_kernel<0, 0, 1><<<dim3(32, 16, 1), blk>>>(x, Wq, pQ, DIM, DIM, HEADS * DIM, 0, 0, 0, 0, bq);
    gemm_kernel<0, 0, 1><<<dim3(32, 16, 1), blk>>>(y, Wk, pK, DIM, DIM, HEADS * DIM, 0, 0, 0, 0, bk);
    gemm_kernel<0, 0, 1><<<dim3(32, 16, 1), blk>>>(y, Wv, pV, DIM, DIM, HEADS * DIM, 0, 0, 0, 0, bv);

    // xp = x @ Wp : M=2048, N=512, K=512
    gemm_kernel<0, 0, 0><<<dim3(4, 16, 1), blk>>>(x, Wp, pXP, DIM, DIM, DIM, DIM, 0, 0, 0, nullptr);

    // E[z] = Q[z] @ K[z]^T (+ column mask): z=16 batches, M=N=1024, K=512
    gemm_kernel<0, 1, 2><<<dim3(8, 8, HB), blk>>>(pQ, pK, pE, DIM, DIM, DIM, SEQ, sQKV, sQKV, sE, nullptr);

    // softmax over rows of E
    softmax_kernel<<<HB * SEQ, 256>>>(pE);

    // out[z] = A[z]^T @ V[z] with gamma/xp blend fused: M=1024 (t), N=512 (d), K=1024 (s)
    gemm_kernel<1, 0, 3><<<dim3(4, 8, HB), blk>>>(pE, pV, out, SEQ, SEQ, DIM, 0, sE, sQKV, 0, gamma);

    (void)in_sizes; (void)n_in; (void)out_size;
}

// round 4
// speedup vs baseline: 1.9994x; 1.9994x over previous
#include <cuda_runtime.h>
#include <cuda_bf16.h>
#include <cstdint>

// ---------------------------------------------------------------------------
// Problem constants
// ---------------------------------------------------------------------------
namespace cfg {
constexpr int BATCH = 2;
constexpr int SEQ   = 1024;
constexpr int DIM   = 512;
constexpr int HEADS = 8;
constexpr int HB    = HEADS * BATCH;
constexpr float NEGINF = -1e30f;
}

// ---------------------------------------------------------------------------
// Device scratch
// ---------------------------------------------------------------------------
__device__ __nv_bfloat16 g_xhi [2048 * 512];
__device__ __nv_bfloat16 g_xlo [2048 * 512];
__device__ __nv_bfloat16 g_Wqt_hi[4096 * 512], g_Wqt_lo[4096 * 512];
__device__ __nv_bfloat16 g_Wkt_hi[4096 * 512], g_Wkt_lo[4096 * 512];
__device__ __nv_bfloat16 g_Wvt_hi[4096 * 512], g_Wvt_lo[4096 * 512];
__device__ __nv_bfloat16 g_Wpt_hi[512 * 512],  g_Wpt_lo[512 * 512];
__device__ __nv_bfloat16 g_Qhi[(size_t)16 * 1024 * 512], g_Qlo[(size_t)16 * 1024 * 512];
__device__ __nv_bfloat16 g_Khi[(size_t)16 * 1024 * 512], g_Klo[(size_t)16 * 1024 * 512];
__device__ float         g_Vf [(size_t)16 * 1024 * 512];
__device__ __nv_bfloat16 g_Vthi[(size_t)16 * 512 * 1024], g_Vtlo[(size_t)16 * 512 * 1024];
__device__ float         g_E  [(size_t)16 * 1024 * 1024];
__device__ __nv_bfloat16 g_Athi[(size_t)16 * 1024 * 1024], g_Atlo[(size_t)16 * 1024 * 1024];
__device__ float         g_XP [2048 * 512];
__device__ float         g_maskAdd[cfg::SEQ];

// ---------------------------------------------------------------------------
// PTX helpers — ONLY stable (non-"a") instructions: cp.async / ldmatrix / mma.sync
// ---------------------------------------------------------------------------
__device__ __forceinline__ uint32_t smem_u32(const void* p) {
    uint32_t a;
    asm("{ .reg .u64 t; cvta.to.shared.u64 t, %1; cvt.u32.u64 %0, t; }" : "=r"(a) : "l"(p));
    return a;
}
__device__ __forceinline__ void cpasync16(uint32_t s, const void* g) {
    asm volatile("cp.async.cg.shared.global [%0], [%1], 16;" :: "r"(s), "l"(g));
}
#define CP_COMMIT()  asm volatile("cp.async.commit_group;" ::: "memory")
#define CP_WAIT(n)   asm volatile("cp.async.wait_group %0;" :: "n"(n) : "memory")
#define LDSM4(r0, r1, r2, r3, a) \
    asm volatile("ldmatrix.sync.aligned.m8n8.x4.shared.b16 {%0,%1,%2,%3}, [%4];" \
        : "=r"(r0), "=r"(r1), "=r"(r2), "=r"(r3) : "r"(a))
#define MMA16816(c, a, b) \
    asm volatile("mma.sync.aligned.m16n8k16.row.col.f32.bf16.bf16.f32 " \
        "{%0,%1,%2,%3}, {%4,%5,%6,%7}, {%8,%9}, {%0,%1,%2,%3};" \
        : "+f"((c)[0]), "+f"((c)[1]), "+f"((c)[2]), "+f"((c)[3]) \
        : "r"((a)[0]), "r"((a)[1]), "r"((a)[2]), "r"((a)[3]), "r"((b)[0]), "r"((b)[1]))

__device__ __forceinline__ uint32_t pack_bf16(float a, float b) {
    __nv_bfloat16 x = __float2bfloat16(a), y = __float2bfloat16(b);
    uint16_t xa = *reinterpret_cast<uint16_t*>(&x);
    uint16_t yb = *reinterpret_cast<uint16_t*>(&y);
    return (uint32_t)xa | ((uint32_t)yb << 16);
}

// ---------------------------------------------------------------------------
// Mask decode (dtype sniffing)
// ---------------------------------------------------------------------------
__global__ void decode_mask_kernel(const unsigned char* __restrict__ mraw) {
    __shared__ int flags[2];
    const int t = threadIdx.x;
    if (t < 2) flags[t] = 0;
    __syncthreads();
    const unsigned char bch = mraw[t];
    if (((t & 3) == 3) && bch == 0x3F) atomicOr(&flags[0], 1);
    if (((t & 3) != 0) && bch != 0)    atomicOr(&flags[1], 1);
    __syncthreads();
    bool valid;
    if (flags[0])      valid = reinterpret_cast<const float*>(mraw)[t] != 0.0f;
    else if (flags[1]) valid = (bch != 0);
    else               valid = reinterpret_cast<const int*>(mraw)[t] != 0;
    g_maskAdd[t] = valid ? 0.0f : cfg::NEGINF;
}

// ---------------------------------------------------------------------------
// fp32 -> bf16 hi/lo split (elementwise)
// ---------------------------------------------------------------------------
__global__ void conv_split_kernel(const float* __restrict__ in,
                                  __nv_bfloat16* __restrict__ hi,
                                  __nv_bfloat16* __restrict__ lo, int n) {
    for (int i = blockIdx.x * blockDim.x + threadIdx.x; i < n; i += gridDim.x * blockDim.x) {
        float v = in[i];
        __nv_bfloat16 h = __float2bfloat16(v);
        hi[i] = h;
        lo[i] = __float2bfloat16(v - __bfloat162float(h));
    }
}

// ---------------------------------------------------------------------------
// Transpose + split: in (z,R,C) fp32 -> out (z,C,R) bf16 hi/lo
// ---------------------------------------------------------------------------
__global__ void transconv_kernel(const float* __restrict__ in,
                                 __nv_bfloat16* __restrict__ hi,
                                 __nv_bfloat16* __restrict__ lo, int R, int C) {
    __shared__ float t[32][33];
    const size_t zoff = (size_t)blockIdx.z * R * C;
    const int c0 = blockIdx.x * 32, r0 = blockIdx.y * 32;
    const int tx = threadIdx.x, ty = threadIdx.y;
#pragma unroll
    for (int i = 0; i < 32; i += 8)
        t[ty + i][tx] = in[zoff + (size_t)(r0 + ty + i) * C + c0 + tx];
    __syncthreads();
#pragma unroll
    for (int i = 0; i < 32; i += 8) {
        float v = t[tx][ty + i];
        __nv_bfloat16 h = __float2bfloat16(v);
        size_t o = zoff + (size_t)(c0 + ty + i) * R + r0 + tx;
        hi[o] = h;
        lo[o] = __float2bfloat16(v - __bfloat162float(h));
    }
}

// ---------------------------------------------------------------------------
// Row softmax (16384 rows x 1024)
// ---------------------------------------------------------------------------
__global__ void softmax_kernel(float* __restrict__ E) {
    const size_t row = blockIdx.x;
    float4* p = reinterpret_cast<float4*>(E + row * cfg::SEQ);
    const int tid = threadIdx.x;
    float4 v = p[tid];
    __shared__ float red[8];

    float m = fmaxf(fmaxf(v.x, v.y), fmaxf(v.z, v.w));
#pragma unroll
    for (int o = 16; o > 0; o >>= 1) m = fmaxf(m, __shfl_xor_sync(0xffffffffu, m, o));
    if ((tid & 31) == 0) red[tid >> 5] = m;
    __syncthreads();
    if (tid == 0) {
        float mm = red[0];
#pragma unroll
        for (int i = 1; i < 8; i++) mm = fmaxf(mm, red[i]);
        red[0] = mm;
    }
    __syncthreads();
    m = red[0];
    __syncthreads();

    v.x = __expf(v.x - m); v.y = __expf(v.y - m);
    v.z = __expf(v.z - m); v.w = __expf(v.w - m);
    float s = v.x + v.y + v.z + v.w;
#pragma unroll
    for (int o = 16; o > 0; o >>= 1) s += __shfl_xor_sync(0xffffffffu, s, o);
    if ((tid & 31) == 0) red[tid >> 5] = s;
    __syncthreads();
    if (tid == 0) {
        float ss = red[0];
#pragma unroll
        for (int i = 1; i < 8; i++) ss += red[i];
        red[0] = ss;
    }
    __syncthreads();
    const float inv = 1.0f / red[0];
    v.x *= inv; v.y *= inv; v.z *= inv; v.w *= inv;
    p[tid] = v;
}

// ---------------------------------------------------------------------------
// mma.sync batched GEMM, 128x128x32 tiles, bf16 3-term fp32 emulation.
//   C[m,n] = sum_k A[m,k]*B[n,k]  (both K-major, hi/lo pre-split in gmem)
//   8 warps, warp tile 32(m) x 64(n); cp.async double buffer.
//   EPI 0: +bias, head relayout -> bf16 hi/lo (Q/K)
//   EPI 1: +bias, head relayout -> fp32 (V)
//   EPI 2: plain fp32 (xp)
//   EPI 3: +maskAdd[n] -> g_E
//   EPI 4: gamma/xp blend -> final output (b,h,t,dv)
// ---------------------------------------------------------------------------
constexpr int BK       = 32;
constexpr int SSTRIDE  = 80;                    // bytes per smem row (40 bf16): bank-stagger
constexpr int PAN_B    = 128 * SSTRIDE;         // 10240 B per panel
constexpr int STAGE_B  = 4 * PAN_B;             // Ahi,Alo,Bhi,Blo
constexpr int DYN_SMEM = 2 * STAGE_B;           // 81920 B

template<int EPI>
__global__ __launch_bounds__(256, 1)
void mma_gemm(const __nv_bfloat16* __restrict__ Ahi, const __nv_bfloat16* __restrict__ Alo,
              const __nv_bfloat16* __restrict__ Bhi, const __nv_bfloat16* __restrict__ Blo,
              int K, long long sA, long long sB,
              float* __restrict__ Cf,
              __nv_bfloat16* __restrict__ Chi, __nv_bfloat16* __restrict__ Clo,
              const float* __restrict__ aux)
{
    extern __shared__ char dynraw[];
    const uint32_t sbase = smem_u32(dynraw);

    const int tid  = threadIdx.x;
    const int wid  = tid >> 5;
    const int lane = tid & 31;
    const int bm   = blockIdx.y * 128;
    const int bn   = blockIdx.x * 128;
    const int z    = blockIdx.z;

    Ahi += (size_t)z * sA; Alo += (size_t)z * sA;
    Bhi += (size_t)z * sB; Blo += (size_t)z * sB;

    const __nv_bfloat16* srcs[4] = {
        Ahi + (size_t)bm * K, Alo + (size_t)bm * K,
        Bhi + (size_t)bn * K, Blo + (size_t)bn * K };

    // loader: each thread loads 32B (2x16B chunks) per panel per stage
    const int lrow = tid >> 1;          // 0..127
    const int lkel = (tid & 1) * 16;    // k-element offset 0 or 16

    const int warpM = (wid & 3) * 32;
    const int warpN = (wid >> 2) * 64;

    float acc[2][8][4];
#pragma unroll
    for (int i = 0; i < 2; i++)
#pragma unroll
        for (int j = 0; j < 8; j++)
#pragma unroll
            for (int q = 0; q < 4; q++) acc[i][j][q] = 0.0f;

    const int NK = K >> 5;

    auto load_stage = [&](int stage, int ko) {
        const int kcol = ko * BK + lkel;
        const uint32_t sbs = sbase + stage * STAGE_B + lrow * SSTRIDE + lkel * 2;
#pragma unroll
        for (int p = 0; p < 4; p++) {
            const __nv_bfloat16* g = srcs[p] + (size_t)lrow * K + kcol;
            const uint32_t s = sbs + p * PAN_B;
            cpasync16(s, g);
            cpasync16(s + 16, g + 8);
        }
        CP_COMMIT();
    };

    load_stage(0, 0);
    load_stage(1, 1);

    // ldmatrix lane addressing (bytes)
    const int rA  = lane & 15;                       // row within 16-row tile
    const int kaA = ((lane & 16) >> 4) * 16;         // k-half byte offset
    const int rB  = (lane & 7) + ((lane & 16) >> 1); // row within 16-row n-pair
    const int kbB = ((lane & 8) >> 3) * 16;

    for (int ko = 0; ko < NK; ko++) {
        if (ko + 1 < NK) { CP_WAIT(1); } else { CP_WAIT(0); }
        __syncthreads();

        const uint32_t st = sbase + (ko & 1) * STAGE_B;
        const uint32_t pAh = st, pAl = st + PAN_B, pBh = st + 2 * PAN_B, pBl = st + 3 * PAN_B;

#pragma unroll
        for (int ks = 0; ks < 2; ks++) {
            const int kb = ks * 32;
            uint32_t ahi[2][4], alo[2][4];
#pragma unroll
            for (int mi = 0; mi < 2; mi++) {
                const uint32_t offA = (uint32_t)((warpM + mi * 16 + rA) * SSTRIDE + kb + kaA);
                LDSM4(ahi[mi][0], ahi[mi][1], ahi[mi][2], ahi[mi][3], pAh + offA);
                LDSM4(alo[mi][0], alo[mi][1], alo[mi][2], alo[mi][3], pAl + offA);
            }
            uint32_t bhi[8][2], blo[8][2];
#pragma unroll
            for (int pr = 0; pr < 4; pr++) {
                const uint32_t offB = (uint32_t)((warpN + pr * 16 + rB) * SSTRIDE + kb + kbB);
                LDSM4(bhi[2 * pr][0], bhi[2 * pr][1], bhi[2 * pr + 1][0], bhi[2 * pr + 1][1],
                      pBh + offB);
                LDSM4(blo[2 * pr][0], blo[2 * pr][1], blo[2 * pr + 1][0], blo[2 * pr + 1][1],
                      pBl + offB);
            }
#pragma unroll
            for (int mi = 0; mi < 2; mi++)
#pragma unroll
                for (int nj = 0; nj < 8; nj++) {
                    MMA16816(acc[mi][nj], ahi[mi], bhi[nj]);
                    MMA16816(acc[mi][nj], ahi[mi], blo[nj]);
                    MMA16816(acc[mi][nj], alo[mi], bhi[nj]);
                }
        }
        __syncthreads();
        if (ko + 2 < NK) load_stage(ko & 1, ko + 2);
    }

    // ---------------- epilogue ----------------
    const int gid = lane >> 2, tq = lane & 3;
#pragma unroll
    for (int mi = 0; mi < 2; mi++) {
#pragma unroll
        for (int h2 = 0; h2 < 2; h2++) {
            const int m = bm + warpM + mi * 16 + gid + h2 * 8;
#pragma unroll
            for (int nj = 0; nj < 8; nj++) {
                const int n = bn + warpN + nj * 8 + tq * 2;
                float v0 = acc[mi][nj][h2 * 2 + 0];
                float v1 = acc[mi][nj][h2 * 2 + 1];

                if constexpr (EPI == 0) {        // Q/K: bias + relayout + split
                    v0 += aux[n]; v1 += aux[n + 1];
                    const int h = n >> 9, dd = n & 511;
                    const int b = m >> 10, s = m & 1023;
                    const size_t base = ((size_t)((h * 2 + b) * 1024 + s)) * 512 + dd;
                    __nv_bfloat16 h0 = __float2bfloat16(v0);
                    __nv_bfloat16 h1 = __float2bfloat16(v1);
                    float l0 = v0 - __bfloat162float(h0);
                    float l1 = v1 - __bfloat162float(h1);
                    uint16_t u0 = *reinterpret_cast<uint16_t*>(&h0);
                    uint16_t u1 = *reinterpret_cast<uint16_t*>(&h1);
                    *reinterpret_cast<uint32_t*>(Chi + base) = (uint32_t)u0 | ((uint32_t)u1 << 16);
                    *reinterpret_cast<uint32_t*>(Clo + base) = pack_bf16(l0, l1);
                } else if constexpr (EPI == 1) { // V: bias + relayout fp32
                    v0 += aux[n]; v1 += aux[n + 1];
                    const int h = n >> 9, dd = n & 511;
                    const int b = m >> 10, s = m & 1023;
                    float* dst = Cf + ((size_t)((h * 2 + b) * 1024 + s)) * 512 + dd;
                    *reinterpret_cast<float2*>(dst) = make_float2(v0, v1);
                } else if constexpr (EPI == 2) { // xp
                    float* dst = Cf + (size_t)m * 512 + n;
                    *reinterpret_cast<float2*>(dst) = make_float2(v0, v1);
                } else if constexpr (EPI == 3) { // energy + mask
                    float* dst = Cf + (size_t)z * cfg::SEQ * cfg::SEQ + (size_t)m * cfg::SEQ + n;
                    *reinterpret_cast<float2*>(dst) =
                        make_float2(v0 + g_maskAdd[n], v1 + g_maskAdd[n + 1]);
                } else {                         // blend -> (b,h,t,dv)
                    const int h = z >> 1, b = z & 1;
                    const float g = aux[h];
                    const float inv = 1.0f / (g + 1.0f);
                    const float2 x2 = *reinterpret_cast<const float2*>(
                        g_XP + ((size_t)(b * 1024 + m)) * 512 + n);
                    float* dst = Cf + ((size_t)((b * 8 + h) * 1024 + m)) * 512 + n;
                    *reinterpret_cast<float2*>(dst) =
                        make_float2((g * v0 + x2.x) * inv, (g * v1 + x2.y) * inv);
                }
            }
        }
    }
}

// ---------------------------------------------------------------------------
// Launcher
// ---------------------------------------------------------------------------
extern "C" void kernel_launch(void* const* d_in, const int* in_sizes, int n_in,
                              void* d_out, int out_size) {
    using namespace cfg;
    const float* x     = (const float*)d_in[0];
    const float* y     = (const float*)d_in[1];
    const float* Wq    = (const float*)d_in[2];
    const float* bq    = (const float*)d_in[3];
    const float* Wk    = (const float*)d_in[4];
    const float* bk    = (const float*)d_in[5];
    const float* Wv    = (const float*)d_in[6];
    const float* bv    = (const float*)d_in[7];
    const float* Wp    = (const float*)d_in[8];
    const float* gamma = (const float*)d_in[9];
    const unsigned char* mask = (const unsigned char*)d_in[10];
    float* out = (float*)d_out;

    __nv_bfloat16 *xhi, *xlo, *wqh, *wql, *wkh, *wkl, *wvh, *wvl, *wph, *wpl;
    __nv_bfloat16 *qhi, *qlo, *khi, *klo, *vthi, *vtlo, *athi, *atlo;
    float *vf, *pE, *pXP;
    cudaGetSymbolAddress((void**)&xhi, g_xhi);    cudaGetSymbolAddress((void**)&xlo, g_xlo);
    cudaGetSymbolAddress((void**)&wqh, g_Wqt_hi); cudaGetSymbolAddress((void**)&wql, g_Wqt_lo);
    cudaGetSymbolAddress((void**)&wkh, g_Wkt_hi); cudaGetSymbolAddress((void**)&wkl, g_Wkt_lo);
    cudaGetSymbolAddress((void**)&wvh, g_Wvt_hi); cudaGetSymbolAddress((void**)&wvl, g_Wvt_lo);
    cudaGetSymbolAddress((void**)&wph, g_Wpt_hi); cudaGetSymbolAddress((void**)&wpl, g_Wpt_lo);
    cudaGetSymbolAddress((void**)&qhi, g_Qhi);    cudaGetSymbolAddress((void**)&qlo, g_Qlo);
    cudaGetSymbolAddress((void**)&khi, g_Khi);    cudaGetSymbolAddress((void**)&klo, g_Klo);
    cudaGetSymbolAddress((void**)&vf,  g_Vf);
    cudaGetSymbolAddress((void**)&vthi, g_Vthi);  cudaGetSymbolAddress((void**)&vtlo, g_Vtlo);
    cudaGetSymbolAddress((void**)&pE,  g_E);
    cudaGetSymbolAddress((void**)&athi, g_Athi);  cudaGetSymbolAddress((void**)&atlo, g_Atlo);
    cudaGetSymbolAddress((void**)&pXP, g_XP);

    cudaFuncSetAttribute(mma_gemm<0>, cudaFuncAttributeMaxDynamicSharedMemorySize, DYN_SMEM);
    cudaFuncSetAttribute(mma_gemm<1>, cudaFuncAttributeMaxDynamicSharedMemorySize, DYN_SMEM);
    cudaFuncSetAttribute(mma_gemm<2>, cudaFuncAttributeMaxDynamicSharedMemorySize, DYN_SMEM);
    cudaFuncSetAttribute(mma_gemm<3>, cudaFuncAttributeMaxDynamicSharedMemorySize, DYN_SMEM);
    cudaFuncSetAttribute(mma_gemm<4>, cudaFuncAttributeMaxDynamicSharedMemorySize, DYN_SMEM);

    decode_mask_kernel<<<1, 1024>>>(mask);

    conv_split_kernel<<<1024, 256>>>(x, xhi, xlo, 2048 * 512);
    transconv_kernel<<<dim3(128, 16, 1), dim3(32, 8)>>>(Wq, wqh, wql, 512, 4096);
    transconv_kernel<<<dim3(128, 16, 1), dim3(32, 8)>>>(Wk, wkh, wkl, 512, 4096);
    transconv_kernel<<<dim3(128, 16, 1), dim3(32, 8)>>>(Wv, wvh, wvl, 512, 4096);
    transconv_kernel<<<dim3(16, 16, 1),  dim3(32, 8)>>>(Wp, wph, wpl, 512, 512);

    // y split: g_Athi/g_Atlo double as temporary y-split buffers (only needed
    // as attn-transpose storage after the projections; stream order keeps it safe)
    conv_split_kernel<<<1024, 256>>>(y, athi, atlo, 2048 * 512);

    // Projections (M=2048, N=4096, K=512)
    mma_gemm<0><<<dim3(32, 16, 1), 256, DYN_SMEM>>>(xhi, xlo, wqh, wql, 512, 0, 0,
                                                    nullptr, qhi, qlo, bq);
    mma_gemm<0><<<dim3(32, 16, 1), 256, DYN_SMEM>>>(athi, atlo, wkh, wkl, 512, 0, 0,
                                                    nullptr, khi, klo, bk);
    mma_gemm<1><<<dim3(32, 16, 1), 256, DYN_SMEM>>>(athi, atlo, wvh, wvl, 512, 0, 0,
                                                    vf, nullptr, nullptr, bv);
    // xp (M=2048, N=512, K=512)
    mma_gemm<2><<<dim3(4, 16, 1), 256, DYN_SMEM>>>(xhi, xlo, wph, wpl, 512, 0, 0,
                                                   pXP, nullptr, nullptr, nullptr);

    // V transpose+split: (z,1024,512) -> (z,512,1024)
    transconv_kernel<<<dim3(16, 32, HB), dim3(32, 8)>>>(vf, vthi, vtlo, 1024, 512);

    // Energy: E[z] = Q[z] K[z]^T + mask (M=N=1024, K=512, z=16)
    const long long sQK = (long long)SEQ * DIM;
    mma_gemm<3><<<dim3(8, 8, HB), 256, DYN_SMEM>>>(qhi, qlo, khi, klo, 512, sQK, sQK,
                                                   pE, nullptr, nullptr, nullptr);

    softmax_kernel<<<HB * SEQ, 256>>>(pE);

    // attn transpose+split: (z,s,t) -> (z,t,s)
    transconv_kernel<<<dim3(32, 32, HB), dim3(32, 8)>>>(pE, athi, atlo, 1024, 1024);

    // out[z] = attnT[z] @ V[z] + blend (M=1024 t, N=512 dv, K=1024 s)
    mma_gemm<4><<<dim3(4, 8, HB), 256, DYN_SMEM>>>(athi, atlo, vthi, vtlo, 1024,
                                                   (long long)SEQ * SEQ, (long long)DIM * SEQ,
                                                   out, nullptr, nullptr, gamma);

    (void)in_sizes; (void)n_in; (void)out_size;
}

// round 5
// speedup vs baseline: 2.5180x; 1.2593x over previous
#include <cuda_runtime.h>
#include <cuda_bf16.h>
#include <cstdint>

// ---------------------------------------------------------------------------
// Problem constants
// ---------------------------------------------------------------------------
namespace cfg {
constexpr int BATCH = 2;
constexpr int SEQ   = 1024;
constexpr int DIM   = 512;
constexpr int HEADS = 8;
constexpr int HB    = HEADS * BATCH;
constexpr float NEGINF = -1e30f;
}

// ---------------------------------------------------------------------------
// Device scratch
// ---------------------------------------------------------------------------
__device__ __nv_bfloat16 g_xhi [2048 * 512];
__device__ __nv_bfloat16 g_xlo [2048 * 512];
__device__ __nv_bfloat16 g_Wqt_hi[4096 * 512], g_Wqt_lo[4096 * 512];
__device__ __nv_bfloat16 g_Wkt_hi[4096 * 512], g_Wkt_lo[4096 * 512];
__device__ __nv_bfloat16 g_Wvt_hi[4096 * 512], g_Wvt_lo[4096 * 512];
__device__ __nv_bfloat16 g_Wpt_hi[512 * 512],  g_Wpt_lo[512 * 512];
__device__ __nv_bfloat16 g_Qhi[(size_t)16 * 1024 * 512], g_Qlo[(size_t)16 * 1024 * 512];
__device__ __nv_bfloat16 g_Khi[(size_t)16 * 1024 * 512], g_Klo[(size_t)16 * 1024 * 512];
__device__ __nv_bfloat16 g_Vhi[(size_t)16 * 1024 * 512], g_Vlo[(size_t)16 * 1024 * 512]; // (z,s,dv)
__device__ float         g_E  [(size_t)16 * 1024 * 1024];                                // (z,s,t)
__device__ __nv_bfloat16 g_Ahi[(size_t)16 * 1024 * 1024], g_Alo[(size_t)16 * 1024 * 1024]; // (z,s,t)
__device__ float         g_XP [2048 * 512];
__device__ float         g_maskAdd[cfg::SEQ];

// ---------------------------------------------------------------------------
// PTX helpers — stable (non-"a") instructions only
// ---------------------------------------------------------------------------
__device__ __forceinline__ uint32_t smem_u32(const void* p) {
    uint32_t a;
    asm("{ .reg .u64 t; cvta.to.shared.u64 t, %1; cvt.u32.u64 %0, t; }" : "=r"(a) : "l"(p));
    return a;
}
__device__ __forceinline__ void cpasync16(uint32_t s, const void* g) {
    asm volatile("cp.async.cg.shared.global [%0], [%1], 16;" :: "r"(s), "l"(g));
}
#define CP_COMMIT()  asm volatile("cp.async.commit_group;" ::: "memory")
#define CP_WAIT(n)   asm volatile("cp.async.wait_group %0;" :: "n"(n) : "memory")
#define LDSM4(r0, r1, r2, r3, a) \
    asm volatile("ldmatrix.sync.aligned.m8n8.x4.shared.b16 {%0,%1,%2,%3}, [%4];" \
        : "=r"(r0), "=r"(r1), "=r"(r2), "=r"(r3) : "r"(a))
#define LDSM4T(r0, r1, r2, r3, a) \
    asm volatile("ldmatrix.sync.aligned.m8n8.x4.trans.shared.b16 {%0,%1,%2,%3}, [%4];" \
        : "=r"(r0), "=r"(r1), "=r"(r2), "=r"(r3) : "r"(a))
#define MMA16816(c, a, b) \
    asm volatile("mma.sync.aligned.m16n8k16.row.col.f32.bf16.bf16.f32 " \
        "{%0,%1,%2,%3}, {%4,%5,%6,%7}, {%8,%9}, {%0,%1,%2,%3};" \
        : "+f"((c)[0]), "+f"((c)[1]), "+f"((c)[2]), "+f"((c)[3]) \
        : "r"((a)[0]), "r"((a)[1]), "r"((a)[2]), "r"((a)[3]), "r"((b)[0]), "r"((b)[1]))

__device__ __forceinline__ uint32_t pack_bf16(float a, float b) {
    __nv_bfloat16 x = __float2bfloat16(a), y = __float2bfloat16(b);
    uint16_t xa = *reinterpret_cast<uint16_t*>(&x);
    uint16_t yb = *reinterpret_cast<uint16_t*>(&y);
    return (uint32_t)xa | ((uint32_t)yb << 16);
}

// ---------------------------------------------------------------------------
// Mask decode (dtype sniffing)
// ---------------------------------------------------------------------------
__global__ void decode_mask_kernel(const unsigned char* __restrict__ mraw) {
    __shared__ int flags[2];
    const int t = threadIdx.x;
    if (t < 2) flags[t] = 0;
    __syncthreads();
    const unsigned char bch = mraw[t];
    if (((t & 3) == 3) && bch == 0x3F) atomicOr(&flags[0], 1);
    if (((t & 3) != 0) && bch != 0)    atomicOr(&flags[1], 1);
    __syncthreads();
    bool valid;
    if (flags[0])      valid = reinterpret_cast<const float*>(mraw)[t] != 0.0f;
    else if (flags[1]) valid = (bch != 0);
    else               valid = reinterpret_cast<const int*>(mraw)[t] != 0;
    g_maskAdd[t] = valid ? 0.0f : cfg::NEGINF;
}

// ---------------------------------------------------------------------------
// fp32 -> bf16 hi/lo split (elementwise)
// ---------------------------------------------------------------------------
__global__ void conv_split_kernel(const float* __restrict__ in,
                                  __nv_bfloat16* __restrict__ hi,
                                  __nv_bfloat16* __restrict__ lo, int n) {
    for (int i = blockIdx.x * blockDim.x + threadIdx.x; i < n; i += gridDim.x * blockDim.x) {
        float v = in[i];
        __nv_bfloat16 h = __float2bfloat16(v);
        hi[i] = h;
        lo[i] = __float2bfloat16(v - __bfloat162float(h));
    }
}

// ---------------------------------------------------------------------------
// Transpose + split (weights only): in (R,C) fp32 -> out (C,R) bf16 hi/lo
// ---------------------------------------------------------------------------
__global__ void transconv_kernel(const float* __restrict__ in,
                                 __nv_bfloat16* __restrict__ hi,
                                 __nv_bfloat16* __restrict__ lo, int R, int C) {
    __shared__ float t[32][33];
    const size_t zoff = (size_t)blockIdx.z * R * C;
    const int c0 = blockIdx.x * 32, r0 = blockIdx.y * 32;
    const int tx = threadIdx.x, ty = threadIdx.y;
#pragma unroll
    for (int i = 0; i < 32; i += 8)
        t[ty + i][tx] = in[zoff + (size_t)(r0 + ty + i) * C + c0 + tx];
    __syncthreads();
#pragma unroll
    for (int i = 0; i < 32; i += 8) {
        float v = t[tx][ty + i];
        __nv_bfloat16 h = __float2bfloat16(v);
        size_t o = zoff + (size_t)(c0 + ty + i) * R + r0 + tx;
        hi[o] = h;
        lo[o] = __float2bfloat16(v - __bfloat162float(h));
    }
}

// ---------------------------------------------------------------------------
// Row softmax fused with bf16 hi/lo split: E fp32 (z,s,t) -> Ahi/Alo bf16
// ---------------------------------------------------------------------------
__global__ void softmax_split_kernel(const float* __restrict__ E,
                                     __nv_bfloat16* __restrict__ hi,
                                     __nv_bfloat16* __restrict__ lo) {
    const size_t row = blockIdx.x;
    const float4* p = reinterpret_cast<const float4*>(E + row * cfg::SEQ);
    const int tid = threadIdx.x;
    float4 v = p[tid];
    __shared__ float red[8];

    float m = fmaxf(fmaxf(v.x, v.y), fmaxf(v.z, v.w));
#pragma unroll
    for (int o = 16; o > 0; o >>= 1) m = fmaxf(m, __shfl_xor_sync(0xffffffffu, m, o));
    if ((tid & 31) == 0) red[tid >> 5] = m;
    __syncthreads();
    if (tid == 0) {
        float mm = red[0];
#pragma unroll
        for (int i = 1; i < 8; i++) mm = fmaxf(mm, red[i]);
        red[0] = mm;
    }
    __syncthreads();
    m = red[0];
    __syncthreads();

    v.x = __expf(v.x - m); v.y = __expf(v.y - m);
    v.z = __expf(v.z - m); v.w = __expf(v.w - m);
    float s = v.x + v.y + v.z + v.w;
#pragma unroll
    for (int o = 16; o > 0; o >>= 1) s += __shfl_xor_sync(0xffffffffu, s, o);
    if ((tid & 31) == 0) red[tid >> 5] = s;
    __syncthreads();
    if (tid == 0) {
        float ss = red[0];
#pragma unroll
        for (int i = 1; i < 8; i++) ss += red[i];
        red[0] = ss;
    }
    __syncthreads();
    const float inv = 1.0f / red[0];
    v.x *= inv; v.y *= inv; v.z *= inv; v.w *= inv;

    float a[4] = {v.x, v.y, v.z, v.w};
    uint32_t hw[2], lw[2];
#pragma unroll
    for (int j = 0; j < 2; j++) {
        __nv_bfloat16 h0 = __float2bfloat16(a[2 * j]);
        __nv_bfloat16 h1 = __float2bfloat16(a[2 * j + 1]);
        float l0 = a[2 * j]     - __bfloat162float(h0);
        float l1 = a[2 * j + 1] - __bfloat162float(h1);
        uint16_t u0 = *reinterpret_cast<uint16_t*>(&h0);
        uint16_t u1 = *reinterpret_cast<uint16_t*>(&h1);
        hw[j] = (uint32_t)u0 | ((uint32_t)u1 << 16);
        lw[j] = pack_bf16(l0, l1);
    }
    const size_t o = row * cfg::SEQ + tid * 4;
    *reinterpret_cast<uint2*>(hi + o) = make_uint2(hw[0], hw[1]);
    *reinterpret_cast<uint2*>(lo + o) = make_uint2(lw[0], lw[1]);
}

// ---------------------------------------------------------------------------
// mma.sync batched GEMM (K-major operands), 128x128x32 tiles, 3-term bf16.
//   EPI 0: +bias, head relayout -> bf16 hi/lo (Q/K/V)
//   EPI 2: plain fp32 (xp)
//   EPI 3: +maskAdd[n] -> g_E
// ---------------------------------------------------------------------------
constexpr int BK       = 32;
constexpr int SSTRIDE  = 80;
constexpr int PAN_B    = 128 * SSTRIDE;
constexpr int STAGE_B  = 4 * PAN_B;
constexpr int DYN_SMEM = 2 * STAGE_B;   // 81920 B

template<int EPI>
__global__ __launch_bounds__(256, 2)
void mma_gemm(const __nv_bfloat16* __restrict__ Ahi, const __nv_bfloat16* __restrict__ Alo,
              const __nv_bfloat16* __restrict__ Bhi, const __nv_bfloat16* __restrict__ Blo,
              int K, long long sA, long long sB,
              float* __restrict__ Cf,
              __nv_bfloat16* __restrict__ Chi, __nv_bfloat16* __restrict__ Clo,
              const float* __restrict__ aux)
{
    extern __shared__ char dynraw[];
    const uint32_t sbase = smem_u32(dynraw);

    const int tid  = threadIdx.x;
    const int wid  = tid >> 5;
    const int lane = tid & 31;
    const int bm   = blockIdx.y * 128;
    const int bn   = blockIdx.x * 128;
    const int z    = blockIdx.z;

    Ahi += (size_t)z * sA; Alo += (size_t)z * sA;
    Bhi += (size_t)z * sB; Blo += (size_t)z * sB;

    const __nv_bfloat16* srcs[4] = {
        Ahi + (size_t)bm * K, Alo + (size_t)bm * K,
        Bhi + (size_t)bn * K, Blo + (size_t)bn * K };

    const int lrow = tid >> 1;
    const int lkel = (tid & 1) * 16;

    const int warpM = (wid & 3) * 32;
    const int warpN = (wid >> 2) * 64;

    float acc[2][8][4];
#pragma unroll
    for (int i = 0; i < 2; i++)
#pragma unroll
        for (int j = 0; j < 8; j++)
#pragma unroll
            for (int q = 0; q < 4; q++) acc[i][j][q] = 0.0f;

    const int NK = K >> 5;

    auto load_stage = [&](int stage, int ko) {
        const int kcol = ko * BK + lkel;
        const uint32_t sbs = sbase + stage * STAGE_B + lrow * SSTRIDE + lkel * 2;
#pragma unroll
        for (int p = 0; p < 4; p++) {
            const __nv_bfloat16* g = srcs[p] + (size_t)lrow * K + kcol;
            const uint32_t s = sbs + p * PAN_B;
            cpasync16(s, g);
            cpasync16(s + 16, g + 8);
        }
        CP_COMMIT();
    };

    load_stage(0, 0);
    load_stage(1, 1);

    const int rA  = lane & 15;
    const int kaA = ((lane & 16) >> 4) * 16;
    const int rB  = (lane & 7) + ((lane & 16) >> 1);
    const int kbB = ((lane & 8) >> 3) * 16;

    for (int ko = 0; ko < NK; ko++) {
        if (ko + 1 < NK) { CP_WAIT(1); } else { CP_WAIT(0); }
        __syncthreads();

        const uint32_t st = sbase + (ko & 1) * STAGE_B;
        const uint32_t pAh = st, pAl = st + PAN_B, pBh = st + 2 * PAN_B, pBl = st + 3 * PAN_B;

#pragma unroll
        for (int ks = 0; ks < 2; ks++) {
            const int kb = ks * 32;
            uint32_t ahi[2][4], alo[2][4];
#pragma unroll
            for (int mi = 0; mi < 2; mi++) {
                const uint32_t offA = (uint32_t)((warpM + mi * 16 + rA) * SSTRIDE + kb + kaA);
                LDSM4(ahi[mi][0], ahi[mi][1], ahi[mi][2], ahi[mi][3], pAh + offA);
                LDSM4(alo[mi][0], alo[mi][1], alo[mi][2], alo[mi][3], pAl + offA);
            }
#pragma unroll
            for (int pr = 0; pr < 4; pr++) {
                uint32_t bh[2][2], bl[2][2];
                const uint32_t offB = (uint32_t)((warpN + pr * 16 + rB) * SSTRIDE + kb + kbB);
                LDSM4(bh[0][0], bh[0][1], bh[1][0], bh[1][1], pBh + offB);
                LDSM4(bl[0][0], bl[0][1], bl[1][0], bl[1][1], pBl + offB);
#pragma unroll
                for (int mi = 0; mi < 2; mi++)
#pragma unroll
                    for (int nb = 0; nb < 2; nb++) {
                        float* a4 = acc[mi][2 * pr + nb];
                        MMA16816(a4, ahi[mi], bh[nb]);
                        MMA16816(a4, ahi[mi], bl[nb]);
                        MMA16816(a4, alo[mi], bh[nb]);
                    }
            }
        }
        __syncthreads();
        if (ko + 2 < NK) load_stage(ko & 1, ko + 2);
    }

    // ---------------- epilogue ----------------
    const int gid = lane >> 2, tq = lane & 3;
#pragma unroll
    for (int mi = 0; mi < 2; mi++) {
#pragma unroll
        for (int h2 = 0; h2 < 2; h2++) {
            const int m = bm + warpM + mi * 16 + gid + h2 * 8;
#pragma unroll
            for (int nj = 0; nj < 8; nj++) {
                const int n = bn + warpN + nj * 8 + tq * 2;
                float v0 = acc[mi][nj][h2 * 2 + 0];
                float v1 = acc[mi][nj][h2 * 2 + 1];

                if constexpr (EPI == 0) {        // bias + head relayout + split
                    v0 += aux[n]; v1 += aux[n + 1];
                    const int h = n >> 9, dd = n & 511;
                    const int b = m >> 10, s = m & 1023;
                    const size_t base = ((size_t)((h * 2 + b) * 1024 + s)) * 512 + dd;
                    __nv_bfloat16 h0 = __float2bfloat16(v0);
                    __nv_bfloat16 h1 = __float2bfloat16(v1);
                    float l0 = v0 - __bfloat162float(h0);
                    float l1 = v1 - __bfloat162float(h1);
                    uint16_t u0 = *reinterpret_cast<uint16_t*>(&h0);
                    uint16_t u1 = *reinterpret_cast<uint16_t*>(&h1);
                    *reinterpret_cast<uint32_t*>(Chi + base) = (uint32_t)u0 | ((uint32_t)u1 << 16);
                    *reinterpret_cast<uint32_t*>(Clo + base) = pack_bf16(l0, l1);
                } else if constexpr (EPI == 2) { // xp
                    float* dst = Cf + (size_t)m * 512 + n;
                    *reinterpret_cast<float2*>(dst) = make_float2(v0, v1);
                } else {                         // EPI 3: energy + mask
                    float* dst = Cf + (size_t)z * cfg::SEQ * cfg::SEQ + (size_t)m * cfg::SEQ + n;
                    *reinterpret_cast<float2*>(dst) =
                        make_float2(v0 + g_maskAdd[n], v1 + g_maskAdd[n + 1]);
                }
            }
        }
    }
}

// ---------------------------------------------------------------------------
// AV GEMM: out[z,t,dv] = sum_s attn[z,s,t] * V[z,s,dv], fused blend epilogue.
// Operands stored MN-major (k=s rows); fragments via ldmatrix.trans.
// ---------------------------------------------------------------------------
constexpr int AV_STRIDE = 272;                 // padded: conflict-free trans loads
constexpr int AV_PAN    = 32 * AV_STRIDE;      // 8704 B
constexpr int AV_STAGE  = 4 * AV_PAN;          // 34816 B
constexpr int AV_SMEM   = 2 * AV_STAGE;        // 69632 B

__global__ __launch_bounds__(256, 2)
void mma_gemm_av(const __nv_bfloat16* __restrict__ Ahi, const __nv_bfloat16* __restrict__ Alo,
                 const __nv_bfloat16* __restrict__ Bhi, const __nv_bfloat16* __restrict__ Blo,
                 float* __restrict__ out, const float* __restrict__ gamma)
{
    extern __shared__ char dynraw[];
    const uint32_t sbase = smem_u32(dynraw);

    const int tid  = threadIdx.x;
    const int wid  = tid >> 5;
    const int lane = tid & 31;
    const int bm   = blockIdx.y * 128;   // t
    const int bn   = blockIdx.x * 128;   // dv
    const int z    = blockIdx.z;

    const size_t sA = (size_t)1024 * 1024, sB = (size_t)1024 * 512;
    const __nv_bfloat16* srcs[4] = {
        Ahi + z * sA + bm, Alo + z * sA + bm,
        Bhi + z * sB + bn, Blo + z * sB + bn };
    const int lens[4] = {1024, 1024, 512, 512};

    const int lrow  = tid >> 3;           // 0..31 (k row)
    const int lcel  = (tid & 7) * 16;     // element offset within 128-col row

    const int warpM = (wid & 3) * 32;
    const int warpN = (wid >> 2) * 64;

    float acc[2][8][4];
#pragma unroll
    for (int i = 0; i < 2; i++)
#pragma unroll
        for (int j = 0; j < 8; j++)
#pragma unroll
            for (int q = 0; q < 4; q++) acc[i][j][q] = 0.0f;

    constexpr int NK = 1024 / 32;

    auto load_stage = [&](int stage, int ko) {
        const int k0 = ko * 32;
        const uint32_t sbs = sbase + stage * AV_STAGE + lrow * AV_STRIDE + lcel * 2;
#pragma unroll
        for (int p = 0; p < 4; p++) {
            const __nv_bfloat16* g = srcs[p] + (size_t)(k0 + lrow) * lens[p] + lcel;
            const uint32_t s = sbs + p * AV_PAN;
            cpasync16(s, g);
            cpasync16(s + 16, g + 8);
        }
        CP_COMMIT();
    };

    load_stage(0, 0);
    load_stage(1, 1);

    // trans-ldmatrix lane addressing (element units for cols, rows of k)
    const int rAk = (lane & 7) + ((lane >> 4) & 1) * 8;   // A: k row within 16
    const int cAm = ((lane >> 3) & 1) * 8;                // A: m col offset
    const int rBk = (lane & 7) + ((lane >> 3) & 1) * 8;   // B: k row within 16
    const int cBn = ((lane >> 4) & 1) * 8;                // B: n col offset

    for (int ko = 0; ko < NK; ko++) {
        if (ko + 1 < NK) { CP_WAIT(1); } else { CP_WAIT(0); }
        __syncthreads();

        const uint32_t st = sbase + (ko & 1) * AV_STAGE;
        const uint32_t pAh = st, pAl = st + AV_PAN, pBh = st + 2 * AV_PAN, pBl = st + 3 * AV_PAN;

#pragma unroll
        for (int ks = 0; ks < 2; ks++) {
            uint32_t ahi[2][4], alo[2][4];
#pragma unroll
            for (int mi = 0; mi < 2; mi++) {
                const uint32_t offA =
                    (uint32_t)((ks * 16 + rAk) * AV_STRIDE + (warpM + mi * 16 + cAm) * 2);
                LDSM4T(ahi[mi][0], ahi[mi][1], ahi[mi][2], ahi[mi][3], pAh + offA);
                LDSM4T(alo[mi][0], alo[mi][1], alo[mi][2], alo[mi][3], pAl + offA);
            }
#pragma unroll
            for (int pr = 0; pr < 4; pr++) {
                uint32_t bh[2][2], bl[2][2];
                const uint32_t offB =
                    (uint32_t)((ks * 16 + rBk) * AV_STRIDE + (warpN + pr * 16 + cBn) * 2);
                LDSM4T(bh[0][0], bh[0][1], bh[1][0], bh[1][1], pBh + offB);
                LDSM4T(bl[0][0], bl[0][1], bl[1][0], bl[1][1], pBl + offB);
#pragma unroll
                for (int mi = 0; mi < 2; mi++)
#pragma unroll
                    for (int nb = 0; nb < 2; nb++) {
                        float* a4 = acc[mi][2 * pr + nb];
                        MMA16816(a4, ahi[mi], bh[nb]);
                        MMA16816(a4, ahi[mi], bl[nb]);
                        MMA16816(a4, alo[mi], bh[nb]);
                    }
            }
        }
        __syncthreads();
        if (ko + 2 < NK) load_stage(ko & 1, ko + 2);
    }

    // ---------------- epilogue: blend -> (b,h,t,dv) ----------------
    const int gid = lane >> 2, tq = lane & 3;
    const int h = z >> 1, b = z & 1;
    const float g = gamma[h];
    const float inv = 1.0f / (g + 1.0f);
#pragma unroll
    for (int mi = 0; mi < 2; mi++) {
#pragma unroll
        for (int h2 = 0; h2 < 2; h2++) {
            const int m = bm + warpM + mi * 16 + gid + h2 * 8;
#pragma unroll
            for (int nj = 0; nj < 8; nj++) {
                const int n = bn + warpN + nj * 8 + tq * 2;
                float v0 = acc[mi][nj][h2 * 2 + 0];
                float v1 = acc[mi][nj][h2 * 2 + 1];
                const float2 x2 = *reinterpret_cast<const float2*>(
                    g_XP + ((size_t)(b * 1024 + m)) * 512 + n);
                float* dst = out + ((size_t)((b * 8 + h) * 1024 + m)) * 512 + n;
                *reinterpret_cast<float2*>(dst) =
                    make_float2((g * v0 + x2.x) * inv, (g * v1 + x2.y) * inv);
            }
        }
    }
}

// ---------------------------------------------------------------------------
// Launcher
// ---------------------------------------------------------------------------
extern "C" void kernel_launch(void* const* d_in, const int* in_sizes, int n_in,
                              void* d_out, int out_size) {
    using namespace cfg;
    const float* x     = (const float*)d_in[0];
    const float* y     = (const float*)d_in[1];
    const float* Wq    = (const float*)d_in[2];
    const float* bq    = (const float*)d_in[3];
    const float* Wk    = (const float*)d_in[4];
    const float* bk    = (const float*)d_in[5];
    const float* Wv    = (const float*)d_in[6];
    const float* bv    = (const float*)d_in[7];
    const float* Wp    = (const float*)d_in[8];
    const float* gamma = (const float*)d_in[9];
    const unsigned char* mask = (const unsigned char*)d_in[10];
    float* out = (float*)d_out;

    __nv_bfloat16 *xhi, *xlo, *wqh, *wql, *wkh, *wkl, *wvh, *wvl, *wph, *wpl;
    __nv_bfloat16 *qhi, *qlo, *khi, *klo, *vhi, *vlo, *ahi, *alo;
    float *pE, *pXP;
    cudaGetSymbolAddress((void**)&xhi, g_xhi);    cudaGetSymbolAddress((void**)&xlo, g_xlo);
    cudaGetSymbolAddress((void**)&wqh, g_Wqt_hi); cudaGetSymbolAddress((void**)&wql, g_Wqt_lo);
    cudaGetSymbolAddress((void**)&wkh, g_Wkt_hi); cudaGetSymbolAddress((void**)&wkl, g_Wkt_lo);
    cudaGetSymbolAddress((void**)&wvh, g_Wvt_hi); cudaGetSymbolAddress((void**)&wvl, g_Wvt_lo);
    cudaGetSymbolAddress((void**)&wph, g_Wpt_hi); cudaGetSymbolAddress((void**)&wpl, g_Wpt_lo);
    cudaGetSymbolAddress((void**)&qhi, g_Qhi);    cudaGetSymbolAddress((void**)&qlo, g_Qlo);
    cudaGetSymbolAddress((void**)&khi, g_Khi);    cudaGetSymbolAddress((void**)&klo, g_Klo);
    cudaGetSymbolAddress((void**)&vhi, g_Vhi);    cudaGetSymbolAddress((void**)&vlo, g_Vlo);
    cudaGetSymbolAddress((void**)&pE,  g_E);
    cudaGetSymbolAddress((void**)&ahi, g_Ahi);    cudaGetSymbolAddress((void**)&alo, g_Alo);
    cudaGetSymbolAddress((void**)&pXP, g_XP);

    cudaFuncSetAttribute(mma_gemm<0>, cudaFuncAttributeMaxDynamicSharedMemorySize, DYN_SMEM);
    cudaFuncSetAttribute(mma_gemm<2>, cudaFuncAttributeMaxDynamicSharedMemorySize, DYN_SMEM);
    cudaFuncSetAttribute(mma_gemm<3>, cudaFuncAttributeMaxDynamicSharedMemorySize, DYN_SMEM);
    cudaFuncSetAttribute(mma_gemm_av, cudaFuncAttributeMaxDynamicSharedMemorySize, AV_SMEM);

    decode_mask_kernel<<<1, 1024>>>(mask);

    conv_split_kernel<<<1024, 256>>>(x, xhi, xlo, 2048 * 512);
    // y split: g_Ahi/g_Alo double as temp y-split buffers (attn overwrites later)
    conv_split_kernel<<<1024, 256>>>(y, ahi, alo, 2048 * 512);

    transconv_kernel<<<dim3(128, 16, 1), dim3(32, 8)>>>(Wq, wqh, wql, 512, 4096);
    transconv_kernel<<<dim3(128, 16, 1), dim3(32, 8)>>>(Wk, wkh, wkl, 512, 4096);
    transconv_kernel<<<dim3(128, 16, 1), dim3(32, 8)>>>(Wv, wvh, wvl, 512, 4096);
    transconv_kernel<<<dim3(16, 16, 1),  dim3(32, 8)>>>(Wp, wph, wpl, 512, 512);

    // Projections (M=2048, N=4096, K=512) -> bf16 hi/lo with head relayout
    mma_gemm<0><<<dim3(32, 16, 1), 256, DYN_SMEM>>>(xhi, xlo, wqh, wql, 512, 0, 0,
                                                    nullptr, qhi, qlo, bq);
    mma_gemm<0><<<dim3(32, 16, 1), 256, DYN_SMEM>>>(ahi, alo, wkh, wkl, 512, 0, 0,
                                                    nullptr, khi, klo, bk);
    mma_gemm<0><<<dim3(32, 16, 1), 256, DYN_SMEM>>>(ahi, alo, wvh, wvl, 512, 0, 0,
                                                    nullptr, vhi, vlo, bv);
    // xp (M=2048, N=512, K=512)
    mma_gemm<2><<<dim3(4, 16, 1), 256, DYN_SMEM>>>(xhi, xlo, wph, wpl, 512, 0, 0,
                                                   pXP, nullptr, nullptr, nullptr);

    // Energy: E[z] = Q[z] K[z]^T + mask (M=N=1024, K=512, z=16)
    const long long sQK = (long long)SEQ * DIM;
    mma_gemm<3><<<dim3(8, 8, HB), 256, DYN_SMEM>>>(qhi, qlo, khi, klo, 512, sQK, sQK,
                                                   pE, nullptr, nullptr, nullptr);

    // softmax + bf16 split (overwrites the y-split scratch with attn)
    softmax_split_kernel<<<HB * SEQ, 256>>>(pE, ahi, alo);

    // AV + blend: trans-ldmatrix consumes attn (s,t) and V (s,dv) directly
    mma_gemm_av<<<dim3(4, 8, HB), 256, AV_SMEM>>>(ahi, alo, vhi, vlo, out, gamma);

    (void)in_sizes; (void)n_in; (void)out_size;
}

// round 6
// speedup vs baseline: 2.5768x; 1.0234x over previous
#include <cuda_runtime.h>
#include <cuda_bf16.h>
#include <cstdint>

namespace cfg {
constexpr int BATCH = 2;
constexpr int SEQ   = 1024;
constexpr int DIM   = 512;
constexpr int HEADS = 8;
constexpr int HB    = HEADS * BATCH;
constexpr float NEGINF = -1e30f;
}

// ---------------------------------------------------------------------------
// Device scratch
// ---------------------------------------------------------------------------
__device__ __nv_bfloat16 g_xhi [2048 * 512];
__device__ __nv_bfloat16 g_xlo [2048 * 512];
__device__ __nv_bfloat16 g_Wqt_hi[4096 * 512], g_Wqt_lo[4096 * 512];
__device__ __nv_bfloat16 g_Wkt_hi[4096 * 512], g_Wkt_lo[4096 * 512];
__device__ __nv_bfloat16 g_Wvt_hi[4096 * 512], g_Wvt_lo[4096 * 512];
__device__ __nv_bfloat16 g_Wpt_hi[512 * 512],  g_Wpt_lo[512 * 512];
__device__ __nv_bfloat16 g_Qhi[(size_t)16 * 1024 * 512], g_Qlo[(size_t)16 * 1024 * 512];
__device__ __nv_bfloat16 g_Khi[(size_t)16 * 1024 * 512], g_Klo[(size_t)16 * 1024 * 512];
__device__ __nv_bfloat16 g_Vhi[(size_t)16 * 1024 * 512], g_Vlo[(size_t)16 * 1024 * 512];
__device__ float         g_E  [(size_t)16 * 1024 * 1024];
__device__ __nv_bfloat16 g_Ahi[(size_t)16 * 1024 * 1024], g_Alo[(size_t)16 * 1024 * 1024];
__device__ float         g_XP [2048 * 512];
__device__ float         g_maskAdd[cfg::SEQ];

// ---------------------------------------------------------------------------
// PTX helpers — stable (non-"a") instructions only
// ---------------------------------------------------------------------------
__device__ __forceinline__ uint32_t smem_u32(const void* p) {
    uint32_t a;
    asm("{ .reg .u64 t; cvta.to.shared.u64 t, %1; cvt.u32.u64 %0, t; }" : "=r"(a) : "l"(p));
    return a;
}
__device__ __forceinline__ void cpasync16(uint32_t s, const void* g) {
    asm volatile("cp.async.cg.shared.global [%0], [%1], 16;" :: "r"(s), "l"(g));
}
#define CP_COMMIT()  asm volatile("cp.async.commit_group;" ::: "memory")
#define CP_WAIT(n)   asm volatile("cp.async.wait_group %0;" :: "n"(n) : "memory")
#define LDSM4(r0, r1, r2, r3, a) \
    asm volatile("ldmatrix.sync.aligned.m8n8.x4.shared.b16 {%0,%1,%2,%3}, [%4];" \
        : "=r"(r0), "=r"(r1), "=r"(r2), "=r"(r3) : "r"(a))
#define LDSM4T(r0, r1, r2, r3, a) \
    asm volatile("ldmatrix.sync.aligned.m8n8.x4.trans.shared.b16 {%0,%1,%2,%3}, [%4];" \
        : "=r"(r0), "=r"(r1), "=r"(r2), "=r"(r3) : "r"(a))
#define MMA16816(c, a, b) \
    asm volatile("mma.sync.aligned.m16n8k16.row.col.f32.bf16.bf16.f32 " \
        "{%0,%1,%2,%3}, {%4,%5,%6,%7}, {%8,%9}, {%0,%1,%2,%3};" \
        : "+f"((c)[0]), "+f"((c)[1]), "+f"((c)[2]), "+f"((c)[3]) \
        : "r"((a)[0]), "r"((a)[1]), "r"((a)[2]), "r"((a)[3]), "r"((b)[0]), "r"((b)[1]))

__device__ __forceinline__ uint32_t pack_bf16(float a, float b) {
    __nv_bfloat16 x = __float2bfloat16(a), y = __float2bfloat16(b);
    uint16_t xa = *reinterpret_cast<uint16_t*>(&x);
    uint16_t yb = *reinterpret_cast<uint16_t*>(&y);
    return (uint32_t)xa | ((uint32_t)yb << 16);
}

// ---------------------------------------------------------------------------
// Mask decode (dtype sniffing)
// ---------------------------------------------------------------------------
__global__ void decode_mask_kernel(const unsigned char* __restrict__ mraw) {
    __shared__ int flags[2];
    const int t = threadIdx.x;
    if (t < 2) flags[t] = 0;
    __syncthreads();
    const unsigned char bch = mraw[t];
    if (((t & 3) == 3) && bch == 0x3F) atomicOr(&flags[0], 1);
    if (((t & 3) != 0) && bch != 0)    atomicOr(&flags[1], 1);
    __syncthreads();
    bool valid;
    if (flags[0])      valid = reinterpret_cast<const float*>(mraw)[t] != 0.0f;
    else if (flags[1]) valid = (bch != 0);
    else               valid = reinterpret_cast<const int*>(mraw)[t] != 0;
    g_maskAdd[t] = valid ? 0.0f : cfg::NEGINF;
}

__global__ void conv_split_kernel(const float* __restrict__ in,
                                  __nv_bfloat16* __restrict__ hi,
                                  __nv_bfloat16* __restrict__ lo, int n) {
    for (int i = blockIdx.x * blockDim.x + threadIdx.x; i < n; i += gridDim.x * blockDim.x) {
        float v = in[i];
        __nv_bfloat16 h = __float2bfloat16(v);
        hi[i] = h;
        lo[i] = __float2bfloat16(v - __bfloat162float(h));
    }
}

__global__ void transconv_kernel(const float* __restrict__ in,
                                 __nv_bfloat16* __restrict__ hi,
                                 __nv_bfloat16* __restrict__ lo, int R, int C) {
    __shared__ float t[32][33];
    const size_t zoff = (size_t)blockIdx.z * R * C;
    const int c0 = blockIdx.x * 32, r0 = blockIdx.y * 32;
    const int tx = threadIdx.x, ty = threadIdx.y;
#pragma unroll
    for (int i = 0; i < 32; i += 8)
        t[ty + i][tx] = in[zoff + (size_t)(r0 + ty + i) * C + c0 + tx];
    __syncthreads();
#pragma unroll
    for (int i = 0; i < 32; i += 8) {
        float v = t[tx][ty + i];
        __nv_bfloat16 h = __float2bfloat16(v);
        size_t o = zoff + (size_t)(c0 + ty + i) * R + r0 + tx;
        hi[o] = h;
        lo[o] = __float2bfloat16(v - __bfloat162float(h));
    }
}

// ---------------------------------------------------------------------------
// Row softmax fused with bf16 hi/lo split
// ---------------------------------------------------------------------------
__global__ void softmax_split_kernel(const float* __restrict__ E,
                                     __nv_bfloat16* __restrict__ hi,
                                     __nv_bfloat16* __restrict__ lo) {
    const size_t row = blockIdx.x;
    const float4* p = reinterpret_cast<const float4*>(E + row * cfg::SEQ);
    const int tid = threadIdx.x;
    float4 v = p[tid];
    __shared__ float red[8];

    float m = fmaxf(fmaxf(v.x, v.y), fmaxf(v.z, v.w));
#pragma unroll
    for (int o = 16; o > 0; o >>= 1) m = fmaxf(m, __shfl_xor_sync(0xffffffffu, m, o));
    if ((tid & 31) == 0) red[tid >> 5] = m;
    __syncthreads();
    if (tid == 0) {
        float mm = red[0];
#pragma unroll
        for (int i = 1; i < 8; i++) mm = fmaxf(mm, red[i]);
        red[0] = mm;
    }
    __syncthreads();
    m = red[0];
    __syncthreads();

    v.x = __expf(v.x - m); v.y = __expf(v.y - m);
    v.z = __expf(v.z - m); v.w = __expf(v.w - m);
    float s = v.x + v.y + v.z + v.w;
#pragma unroll
    for (int o = 16; o > 0; o >>= 1) s += __shfl_xor_sync(0xffffffffu, s, o);
    if ((tid & 31) == 0) red[tid >> 5] = s;
    __syncthreads();
    if (tid == 0) {
        float ss = red[0];
#pragma unroll
        for (int i = 1; i < 8; i++) ss += red[i];
        red[0] = ss;
    }
    __syncthreads();
    const float inv = 1.0f / red[0];
    v.x *= inv; v.y *= inv; v.z *= inv; v.w *= inv;

    float a[4] = {v.x, v.y, v.z, v.w};
    uint32_t hw[2], lw[2];
#pragma unroll
    for (int j = 0; j < 2; j++) {
        __nv_bfloat16 h0 = __float2bfloat16(a[2 * j]);
        __nv_bfloat16 h1 = __float2bfloat16(a[2 * j + 1]);
        float l0 = a[2 * j]     - __bfloat162float(h0);
        float l1 = a[2 * j + 1] - __bfloat162float(h1);
        uint16_t u0 = *reinterpret_cast<uint16_t*>(&h0);
        uint16_t u1 = *reinterpret_cast<uint16_t*>(&h1);
        hw[j] = (uint32_t)u0 | ((uint32_t)u1 << 16);
        lw[j] = pack_bf16(l0, l1);
    }
    const size_t o = row * cfg::SEQ + tid * 4;
    *reinterpret_cast<uint2*>(hi + o) = make_uint2(hw[0], hw[1]);
    *reinterpret_cast<uint2*>(lo + o) = make_uint2(lw[0], lw[1]);
}

// ===========================================================================
// K-major GEMM core: 256x128 CTA tile, 512 threads (16 warps: 8m x 2n),
// 3-stage cp.async pipeline with top-issued loads, K fixed = 512.
// ===========================================================================
constexpr int KSTRIDE = 80;
constexpr int PANA    = 256 * KSTRIDE;            // 20480
constexpr int PANB    = 128 * KSTRIDE;            // 10240
constexpr int KSTAGE  = 2 * PANA + 2 * PANB;      // 61440
constexpr int KSMEM   = 3 * KSTAGE;               // 184320

// loader: per thread 6x cp.async16 covering one full stage
#define K_LOAD_STAGE(stage, ko)                                                   \
    do {                                                                          \
        const int _ar = tid >> 1, _ac = (ko) * 32 + (tid & 1) * 16;               \
        uint32_t _sa = sbase + (stage) * KSTAGE + _ar * KSTRIDE + (tid & 1) * 32; \
        cpasync16(_sa,          pAhi + (size_t)_ar * 512 + _ac);                  \
        cpasync16(_sa + 16,     pAhi + (size_t)_ar * 512 + _ac + 8);              \
        cpasync16(_sa + PANA,      pAlo + (size_t)_ar * 512 + _ac);               \
        cpasync16(_sa + PANA + 16, pAlo + (size_t)_ar * 512 + _ac + 8);           \
        const int _br = tid >> 2, _bc = (ko) * 32 + (tid & 3) * 8;                \
        uint32_t _sb = sbase + (stage) * KSTAGE + 2 * PANA + _br * KSTRIDE + (tid & 3) * 16; \
        cpasync16(_sb,        pBhi + (size_t)_br * 512 + _bc);                    \
        cpasync16(_sb + PANB, pBlo + (size_t)_br * 512 + _bc);                    \
        CP_COMMIT();                                                              \
    } while (0)

#define K_CORE_LOOP()                                                             \
    constexpr int NK = 16;                                                        \
    K_LOAD_STAGE(0, 0);                                                           \
    K_LOAD_STAGE(1, 1);                                                           \
    const int rA  = lane & 15;                                                    \
    const int kaA = ((lane & 16) >> 4) * 16;                                      \
    const int rB  = (lane & 7) + ((lane & 16) >> 1);                              \
    const int kbB = ((lane & 8) >> 3) * 16;                                       \
    int cs = 0, ns = 2;                                                           \
    for (int ko = 0; ko < NK; ko++) {                                             \
        if (ko + 1 < NK) { CP_WAIT(1); } else { CP_WAIT(0); }                     \
        __syncthreads();                                                          \
        if (ko + 2 < NK) { K_LOAD_STAGE(ns, ko + 2); }                            \
        const uint32_t st  = sbase + cs * KSTAGE;                                 \
        const uint32_t pAh = st, pAl = st + PANA;                                 \
        const uint32_t pBh = st + 2 * PANA, pBl = st + 2 * PANA + PANB;           \
        _Pragma("unroll")                                                         \
        for (int ks = 0; ks < 2; ks++) {                                          \
            const int kb = ks * 32;                                               \
            uint32_t ahi[2][4], alo[2][4];                                        \
            _Pragma("unroll")                                                     \
            for (int mi = 0; mi < 2; mi++) {                                      \
                const uint32_t offA = (uint32_t)((warpM + mi * 16 + rA) * KSTRIDE + kb + kaA); \
                LDSM4(ahi[mi][0], ahi[mi][1], ahi[mi][2], ahi[mi][3], pAh + offA);\
                LDSM4(alo[mi][0], alo[mi][1], alo[mi][2], alo[mi][3], pAl + offA);\
            }                                                                     \
            _Pragma("unroll")                                                     \
            for (int pr = 0; pr < 4; pr++) {                                      \
                uint32_t bh[2][2], bl[2][2];                                      \
                const uint32_t offB = (uint32_t)((warpN + pr * 16 + rB) * KSTRIDE + kb + kbB); \
                LDSM4(bh[0][0], bh[0][1], bh[1][0], bh[1][1], pBh + offB);        \
                LDSM4(bl[0][0], bl[0][1], bl[1][0], bl[1][1], pBl + offB);        \
                _Pragma("unroll")                                                 \
                for (int mi = 0; mi < 2; mi++)                                    \
                    _Pragma("unroll")                                             \
                    for (int nb = 0; nb < 2; nb++) {                              \
                        float* a4 = acc[mi][2 * pr + nb];                         \
                        MMA16816(a4, ahi[mi], bh[nb]);                            \
                        MMA16816(a4, ahi[mi], bl[nb]);                            \
                        MMA16816(a4, alo[mi], bh[nb]);                            \
                    }                                                             \
            }                                                                     \
        }                                                                         \
        cs = cs == 2 ? 0 : cs + 1;                                                \
        ns = ns == 2 ? 0 : ns + 1;                                                \
    }

// ---------------------------------------------------------------------------
// Merged QKV + xp projection kernel. grid (32, 8, 4); z: 0=Q 1=K 2=V 3=xp.
// ---------------------------------------------------------------------------
__global__ __launch_bounds__(512, 1)
void gemm_qkv(const __nv_bfloat16* __restrict__ xhi, const __nv_bfloat16* __restrict__ xlo,
              const __nv_bfloat16* __restrict__ yhi, const __nv_bfloat16* __restrict__ ylo,
              const __nv_bfloat16* __restrict__ wqh, const __nv_bfloat16* __restrict__ wql,
              const __nv_bfloat16* __restrict__ wkh, const __nv_bfloat16* __restrict__ wkl,
              const __nv_bfloat16* __restrict__ wvh, const __nv_bfloat16* __restrict__ wvl,
              const __nv_bfloat16* __restrict__ wph, const __nv_bfloat16* __restrict__ wpl,
              const float* __restrict__ bq, const float* __restrict__ bk,
              const float* __restrict__ bv,
              __nv_bfloat16* __restrict__ qhi, __nv_bfloat16* __restrict__ qlo,
              __nv_bfloat16* __restrict__ khi, __nv_bfloat16* __restrict__ klo,
              __nv_bfloat16* __restrict__ vhi, __nv_bfloat16* __restrict__ vlo,
              float* __restrict__ xp)
{
    extern __shared__ char dynraw[];
    const uint32_t sbase = smem_u32(dynraw);
    const int z = blockIdx.z;
    if (z == 3 && blockIdx.x >= 4) return;

    const int tid  = threadIdx.x;
    const int wid  = tid >> 5;
    const int lane = tid & 31;
    const int bm   = blockIdx.y * 256;
    const int bn   = blockIdx.x * 128;

    const __nv_bfloat16* pAhi = ((z == 1 || z == 2) ? yhi : xhi) + (size_t)bm * 512;
    const __nv_bfloat16* pAlo = ((z == 1 || z == 2) ? ylo : xlo) + (size_t)bm * 512;
    const __nv_bfloat16* pBhi = (z == 0 ? wqh : z == 1 ? wkh : z == 2 ? wvh : wph) + (size_t)bn * 512;
    const __nv_bfloat16* pBlo = (z == 0 ? wql : z == 1 ? wkl : z == 2 ? wvl : wpl) + (size_t)bn * 512;
    const float* bias = (z == 0 ? bq : z == 1 ? bk : bv);
    __nv_bfloat16* Chi = (z == 0 ? qhi : z == 1 ? khi : vhi);
    __nv_bfloat16* Clo = (z == 0 ? qlo : z == 1 ? klo : vlo);

    const int warpM = (wid & 7) * 32;
    const int warpN = (wid >> 3) * 64;

    float acc[2][8][4];
#pragma unroll
    for (int i = 0; i < 2; i++)
#pragma unroll
        for (int j = 0; j < 8; j++)
#pragma unroll
            for (int q = 0; q < 4; q++) acc[i][j][q] = 0.0f;

    K_CORE_LOOP();

    const int gid = lane >> 2, tq = lane & 3;
#pragma unroll
    for (int mi = 0; mi < 2; mi++) {
#pragma unroll
        for (int h2 = 0; h2 < 2; h2++) {
            const int m = bm + warpM + mi * 16 + gid + h2 * 8;
#pragma unroll
            for (int nj = 0; nj < 8; nj++) {
                const int n = bn + warpN + nj * 8 + tq * 2;
                float v0 = acc[mi][nj][h2 * 2 + 0];
                float v1 = acc[mi][nj][h2 * 2 + 1];
                if (z < 3) {
                    v0 += bias[n]; v1 += bias[n + 1];
                    const int h = n >> 9, dd = n & 511;
                    const int b = m >> 10, s = m & 1023;
                    const size_t base = ((size_t)((h * 2 + b) * 1024 + s)) * 512 + dd;
                    __nv_bfloat16 h0 = __float2bfloat16(v0);
                    __nv_bfloat16 h1 = __float2bfloat16(v1);
                    float l0 = v0 - __bfloat162float(h0);
                    float l1 = v1 - __bfloat162float(h1);
                    uint16_t u0 = *reinterpret_cast<uint16_t*>(&h0);
                    uint16_t u1 = *reinterpret_cast<uint16_t*>(&h1);
                    *reinterpret_cast<uint32_t*>(Chi + base) = (uint32_t)u0 | ((uint32_t)u1 << 16);
                    *reinterpret_cast<uint32_t*>(Clo + base) = pack_bf16(l0, l1);
                } else {
                    float* dst = xp + (size_t)m * 512 + n;
                    *reinterpret_cast<float2*>(dst) = make_float2(v0, v1);
                }
            }
        }
    }
}

// ---------------------------------------------------------------------------
// Energy kernel: E[z] = Q[z] K[z]^T + mask. grid (8, 4, 16).
// ---------------------------------------------------------------------------
__global__ __launch_bounds__(512, 1)
void gemm_energy(const __nv_bfloat16* __restrict__ qhi, const __nv_bfloat16* __restrict__ qlo,
                 const __nv_bfloat16* __restrict__ khi, const __nv_bfloat16* __restrict__ klo,
                 float* __restrict__ E)
{
    extern __shared__ char dynraw[];
    const uint32_t sbase = smem_u32(dynraw);
    const int tid  = threadIdx.x;
    const int wid  = tid >> 5;
    const int lane = tid & 31;
    const int bm   = blockIdx.y * 256;
    const int bn   = blockIdx.x * 128;
    const int z    = blockIdx.z;

    const size_t sQK = (size_t)cfg::SEQ * cfg::DIM;
    const __nv_bfloat16* pAhi = qhi + z * sQK + (size_t)bm * 512;
    const __nv_bfloat16* pAlo = qlo + z * sQK + (size_t)bm * 512;
    const __nv_bfloat16* pBhi = khi + z * sQK + (size_t)bn * 512;
    const __nv_bfloat16* pBlo = klo + z * sQK + (size_t)bn * 512;

    const int warpM = (wid & 7) * 32;
    const int warpN = (wid >> 3) * 64;

    float acc[2][8][4];
#pragma unroll
    for (int i = 0; i < 2; i++)
#pragma unroll
        for (int j = 0; j < 8; j++)
#pragma unroll
            for (int q = 0; q < 4; q++) acc[i][j][q] = 0.0f;

    K_CORE_LOOP();

    const int gid = lane >> 2, tq = lane & 3;
#pragma unroll
    for (int mi = 0; mi < 2; mi++) {
#pragma unroll
        for (int h2 = 0; h2 < 2; h2++) {
            const int m = bm + warpM + mi * 16 + gid + h2 * 8;
#pragma unroll
            for (int nj = 0; nj < 8; nj++) {
                const int n = bn + warpN + nj * 8 + tq * 2;
                float* dst = E + (size_t)z * cfg::SEQ * cfg::SEQ + (size_t)m * cfg::SEQ + n;
                *reinterpret_cast<float2*>(dst) = make_float2(
                    acc[mi][nj][h2 * 2 + 0] + g_maskAdd[n],
                    acc[mi][nj][h2 * 2 + 1] + g_maskAdd[n + 1]);
            }
        }
    }
}

// ---------------------------------------------------------------------------
// AV kernel: out[z,t,dv] = sum_s attn[z,s,t] * V[z,s,dv], blend epilogue.
// 256(t)x128(dv) tile, 512 threads, 3 stages, trans-ldmatrix. grid (4,4,16).
// ---------------------------------------------------------------------------
constexpr int AV_SA   = 528;                 // A row stride (256 cols + pad)
constexpr int AV_SB   = 272;                 // B row stride (128 cols + pad)
constexpr int AVPANA  = 32 * AV_SA;          // 16896
constexpr int AVPANB  = 32 * AV_SB;          // 8704
constexpr int AVSTAGE = 2 * AVPANA + 2 * AVPANB;  // 51200
constexpr int AVSMEM  = 3 * AVSTAGE;              // 153600

__global__ __launch_bounds__(512, 1)
void gemm_av(const __nv_bfloat16* __restrict__ Ahi, const __nv_bfloat16* __restrict__ Alo,
             const __nv_bfloat16* __restrict__ Bhi, const __nv_bfloat16* __restrict__ Blo,
             float* __restrict__ out, const float* __restrict__ gamma)
{
    extern __shared__ char dynraw[];
    const uint32_t sbase = smem_u32(dynraw);
    const int tid  = threadIdx.x;
    const int wid  = tid >> 5;
    const int lane = tid & 31;
    const int bm   = blockIdx.y * 256;   // t
    const int bn   = blockIdx.x * 128;   // dv
    const int z    = blockIdx.z;

    const size_t sA = (size_t)1024 * 1024, sB = (size_t)1024 * 512;
    const __nv_bfloat16* pAhi = Ahi + z * sA + bm;
    const __nv_bfloat16* pAlo = Alo + z * sA + bm;
    const __nv_bfloat16* pBhi = Bhi + z * sB + bn;
    const __nv_bfloat16* pBlo = Blo + z * sB + bn;

    const int warpM = (wid & 7) * 32;
    const int warpN = (wid >> 3) * 64;

    float acc[2][8][4];
#pragma unroll
    for (int i = 0; i < 2; i++)
#pragma unroll
        for (int j = 0; j < 8; j++)
#pragma unroll
            for (int q = 0; q < 4; q++) acc[i][j][q] = 0.0f;

    constexpr int NK = 32;

    const int ar = tid >> 4, abyte = (tid & 15) * 32;
    const int bbyte = (tid & 15) * 16;

#define AV_LOAD_STAGE(stage, ko)                                                   \
    do {                                                                           \
        const int _k = (ko) * 32 + ar;                                             \
        uint32_t _sa = sbase + (stage) * AVSTAGE + ar * AV_SA + abyte;             \
        cpasync16(_sa,      pAhi + (size_t)_k * 1024 + abyte / 2);                 \
        cpasync16(_sa + 16, pAhi + (size_t)_k * 1024 + abyte / 2 + 8);             \
        cpasync16(_sa + AVPANA,      pAlo + (size_t)_k * 1024 + abyte / 2);        \
        cpasync16(_sa + AVPANA + 16, pAlo + (size_t)_k * 1024 + abyte / 2 + 8);    \
        uint32_t _sb = sbase + (stage) * AVSTAGE + 2 * AVPANA + ar * AV_SB + bbyte;\
        cpasync16(_sb,          pBhi + (size_t)_k * 512 + bbyte / 2);              \
        cpasync16(_sb + AVPANB, pBlo + (size_t)_k * 512 + bbyte / 2);              \
        CP_COMMIT();                                                               \
    } while (0)

    AV_LOAD_STAGE(0, 0);
    AV_LOAD_STAGE(1, 1);

    const int rAk = (lane & 7) + ((lane >> 4) & 1) * 8;
    const int cAm = ((lane >> 3) & 1) * 8;
    const int rBk = (lane & 7) + ((lane >> 3) & 1) * 8;
    const int cBn = ((lane >> 4) & 1) * 8;

    int cs = 0, ns = 2;
    for (int ko = 0; ko < NK; ko++) {
        if (ko + 1 < NK) { CP_WAIT(1); } else { CP_WAIT(0); }
        __syncthreads();
        if (ko + 2 < NK) { AV_LOAD_STAGE(ns, ko + 2); }

        const uint32_t st  = sbase + cs * AVSTAGE;
        const uint32_t pAh = st, pAl = st + AVPANA;
        const uint32_t pBh = st + 2 * AVPANA, pBl = st + 2 * AVPANA + AVPANB;

#pragma unroll
        for (int ks = 0; ks < 2; ks++) {
            uint32_t ahi[2][4], alo[2][4];
#pragma unroll
            for (int mi = 0; mi < 2; mi++) {
                const uint32_t offA =
                    (uint32_t)((ks * 16 + rAk) * AV_SA + (warpM + mi * 16 + cAm) * 2);
                LDSM4T(ahi[mi][0], ahi[mi][1], ahi[mi][2], ahi[mi][3], pAh + offA);
                LDSM4T(alo[mi][0], alo[mi][1], alo[mi][2], alo[mi][3], pAl + offA);
            }
#pragma unroll
            for (int pr = 0; pr < 4; pr++) {
                uint32_t bh[2][2], bl[2][2];
                const uint32_t offB =
                    (uint32_t)((ks * 16 + rBk) * AV_SB + (warpN + pr * 16 + cBn) * 2);
                LDSM4T(bh[0][0], bh[0][1], bh[1][0], bh[1][1], pBh + offB);
                LDSM4T(bl[0][0], bl[0][1], bl[1][0], bl[1][1], pBl + offB);
#pragma unroll
                for (int mi = 0; mi < 2; mi++)
#pragma unroll
                    for (int nb = 0; nb < 2; nb++) {
                        float* a4 = acc[mi][2 * pr + nb];
                        MMA16816(a4, ahi[mi], bh[nb]);
                        MMA16816(a4, ahi[mi], bl[nb]);
                        MMA16816(a4, alo[mi], bh[nb]);
                    }
            }
        }
        cs = cs == 2 ? 0 : cs + 1;
        ns = ns == 2 ? 0 : ns + 1;
    }

    const int gid = lane >> 2, tq = lane & 3;
    const int h = z >> 1, b = z & 1;
    const float g = gamma[h];
    const float inv = 1.0f / (g + 1.0f);
#pragma unroll
    for (int mi = 0; mi < 2; mi++) {
#pragma unroll
        for (int h2 = 0; h2 < 2; h2++) {
            const int m = bm + warpM + mi * 16 + gid + h2 * 8;
#pragma unroll
            for (int nj = 0; nj < 8; nj++) {
                const int n = bn + warpN + nj * 8 + tq * 2;
                float v0 = acc[mi][nj][h2 * 2 + 0];
                float v1 = acc[mi][nj][h2 * 2 + 1];
                const float2 x2 = *reinterpret_cast<const float2*>(
                    g_XP + ((size_t)(b * 1024 + m)) * 512 + n);
                float* dst = out + ((size_t)((b * 8 + h) * 1024 + m)) * 512 + n;
                *reinterpret_cast<float2*>(dst) =
                    make_float2((g * v0 + x2.x) * inv, (g * v1 + x2.y) * inv);
            }
        }
    }
}

// ---------------------------------------------------------------------------
// Launcher
// ---------------------------------------------------------------------------
extern "C" void kernel_launch(void* const* d_in, const int* in_sizes, int n_in,
                              void* d_out, int out_size) {
    using namespace cfg;
    const float* x     = (const float*)d_in[0];
    const float* y     = (const float*)d_in[1];
    const float* Wq    = (const float*)d_in[2];
    const float* bq    = (const float*)d_in[3];
    const float* Wk    = (const float*)d_in[4];
    const float* bk    = (const float*)d_in[5];
    const float* Wv    = (const float*)d_in[6];
    const float* bv    = (const float*)d_in[7];
    const float* Wp    = (const float*)d_in[8];
    const float* gamma = (const float*)d_in[9];
    const unsigned char* mask = (const unsigned char*)d_in[10];
    float* out = (float*)d_out;

    __nv_bfloat16 *xhi, *xlo, *wqh, *wql, *wkh, *wkl, *wvh, *wvl, *wph, *wpl;
    __nv_bfloat16 *qhi, *qlo, *khi, *klo, *vhi, *vlo, *ahi, *alo;
    float *pE, *pXP;
    cudaGetSymbolAddress((void**)&xhi, g_xhi);    cudaGetSymbolAddress((void**)&xlo, g_xlo);
    cudaGetSymbolAddress((void**)&wqh, g_Wqt_hi); cudaGetSymbolAddress((void**)&wql, g_Wqt_lo);
    cudaGetSymbolAddress((void**)&wkh, g_Wkt_hi); cudaGetSymbolAddress((void**)&wkl, g_Wkt_lo);
    cudaGetSymbolAddress((void**)&wvh, g_Wvt_hi); cudaGetSymbolAddress((void**)&wvl, g_Wvt_lo);
    cudaGetSymbolAddress((void**)&wph, g_Wpt_hi); cudaGetSymbolAddress((void**)&wpl, g_Wpt_lo);
    cudaGetSymbolAddress((void**)&qhi, g_Qhi);    cudaGetSymbolAddress((void**)&qlo, g_Qlo);
    cudaGetSymbolAddress((void**)&khi, g_Khi);    cudaGetSymbolAddress((void**)&klo, g_Klo);
    cudaGetSymbolAddress((void**)&vhi, g_Vhi);    cudaGetSymbolAddress((void**)&vlo, g_Vlo);
    cudaGetSymbolAddress((void**)&pE,  g_E);
    cudaGetSymbolAddress((void**)&ahi, g_Ahi);    cudaGetSymbolAddress((void**)&alo, g_Alo);
    cudaGetSymbolAddress((void**)&pXP, g_XP);

    cudaFuncSetAttribute(gemm_qkv,    cudaFuncAttributeMaxDynamicSharedMemorySize, KSMEM);
    cudaFuncSetAttribute(gemm_energy, cudaFuncAttributeMaxDynamicSharedMemorySize, KSMEM);
    cudaFuncSetAttribute(gemm_av,     cudaFuncAttributeMaxDynamicSharedMemorySize, AVSMEM);

    decode_mask_kernel<<<1, 1024>>>(mask);

    conv_split_kernel<<<1024, 256>>>(x, xhi, xlo, 2048 * 512);
    // y split: g_Ahi/g_Alo double as temp y-split buffers (attn overwrites later)
    conv_split_kernel<<<1024, 256>>>(y, ahi, alo, 2048 * 512);

    transconv_kernel<<<dim3(128, 16, 1), dim3(32, 8)>>>(Wq, wqh, wql, 512, 4096);
    transconv_kernel<<<dim3(128, 16, 1), dim3(32, 8)>>>(Wk, wkh, wkl, 512, 4096);
    transconv_kernel<<<dim3(128, 16, 1), dim3(32, 8)>>>(Wv, wvh, wvl, 512, 4096);
    transconv_kernel<<<dim3(16, 16, 1),  dim3(32, 8)>>>(Wp, wph, wpl, 512, 512);

    // Merged Q/K/V/xp projections
    gemm_qkv<<<dim3(32, 8, 4), 512, KSMEM>>>(xhi, xlo, ahi, alo,
                                             wqh, wql, wkh, wkl, wvh, wvl, wph, wpl,
                                             bq, bk, bv,
                                             qhi, qlo, khi, klo, vhi, vlo, pXP);

    // Energy + mask
    gemm_energy<<<dim3(8, 4, HB), 512, KSMEM>>>(qhi, qlo, khi, klo, pE);

    // softmax + bf16 split (overwrites the y-split scratch with attn)
    softmax_split_kernel<<<HB * SEQ, 256>>>(pE, ahi, alo);

    // AV + blend
    gemm_av<<<dim3(4, 4, HB), 512, AVSMEM>>>(ahi, alo, vhi, vlo, out, gamma);

    (void)in_sizes; (void)n_in; (void)out_size;
}

// round 7
// speedup vs baseline: 2.7725x; 1.0759x over previous
#include <cuda_runtime.h>
#include <cuda_bf16.h>
#include <cstdint>

namespace cfg {
constexpr int BATCH = 2;
constexpr int SEQ   = 1024;
constexpr int DIM   = 512;
constexpr int HEADS = 8;
constexpr int HB    = HEADS * BATCH;
constexpr float NEGINF = -1e30f;
}

// ---------------------------------------------------------------------------
// Device scratch
// ---------------------------------------------------------------------------
__device__ __nv_bfloat16 g_xhi [2048 * 512];
__device__ __nv_bfloat16 g_xlo [2048 * 512];
__device__ __nv_bfloat16 g_Wqt_hi[4096 * 512], g_Wqt_lo[4096 * 512];
__device__ __nv_bfloat16 g_Wkt_hi[4096 * 512], g_Wkt_lo[4096 * 512];
__device__ __nv_bfloat16 g_Wvt_hi[4096 * 512], g_Wvt_lo[4096 * 512];
__device__ __nv_bfloat16 g_Wpt_hi[512 * 512],  g_Wpt_lo[512 * 512];
__device__ __nv_bfloat16 g_Qhi[(size_t)16 * 1024 * 512], g_Qlo[(size_t)16 * 1024 * 512];
__device__ __nv_bfloat16 g_Khi[(size_t)16 * 1024 * 512], g_Klo[(size_t)16 * 1024 * 512];
__device__ __nv_bfloat16 g_Vhi[(size_t)16 * 1024 * 512];           // V only needed at bf16
__device__ float         g_E  [(size_t)16 * 1024 * 1024];
__device__ __nv_bfloat16 g_Ahi[(size_t)16 * 1024 * 1024], g_Alo[(size_t)16 * 1024 * 1024];
__device__ float         g_XP [2048 * 512];
__device__ float         g_maskAdd[cfg::SEQ];

// ---------------------------------------------------------------------------
// PTX helpers — stable (non-"a") instructions only
// ---------------------------------------------------------------------------
__device__ __forceinline__ uint32_t smem_u32(const void* p) {
    uint32_t a;
    asm("{ .reg .u64 t; cvta.to.shared.u64 t, %1; cvt.u32.u64 %0, t; }" : "=r"(a) : "l"(p));
    return a;
}
__device__ __forceinline__ void cpasync16(uint32_t s, const void* g) {
    asm volatile("cp.async.cg.shared.global [%0], [%1], 16;" :: "r"(s), "l"(g));
}
#define CP_COMMIT()  asm volatile("cp.async.commit_group;" ::: "memory")
#define CP_WAIT(n)   asm volatile("cp.async.wait_group %0;" :: "n"(n) : "memory")
#define LDSM4(r0, r1, r2, r3, a) \
    asm volatile("ldmatrix.sync.aligned.m8n8.x4.shared.b16 {%0,%1,%2,%3}, [%4];" \
        : "=r"(r0), "=r"(r1), "=r"(r2), "=r"(r3) : "r"(a))
#define LDSM4T(r0, r1, r2, r3, a) \
    asm volatile("ldmatrix.sync.aligned.m8n8.x4.trans.shared.b16 {%0,%1,%2,%3}, [%4];" \
        : "=r"(r0), "=r"(r1), "=r"(r2), "=r"(r3) : "r"(a))
#define MMA16816(c, a, b) \
    asm volatile("mma.sync.aligned.m16n8k16.row.col.f32.bf16.bf16.f32 " \
        "{%0,%1,%2,%3}, {%4,%5,%6,%7}, {%8,%9}, {%0,%1,%2,%3};" \
        : "+f"((c)[0]), "+f"((c)[1]), "+f"((c)[2]), "+f"((c)[3]) \
        : "r"((a)[0]), "r"((a)[1]), "r"((a)[2]), "r"((a)[3]), "r"((b)[0]), "r"((b)[1]))

__device__ __forceinline__ uint32_t pack_bf16(float a, float b) {
    __nv_bfloat16 x = __float2bfloat16(a), y = __float2bfloat16(b);
    uint16_t xa = *reinterpret_cast<uint16_t*>(&x);
    uint16_t yb = *reinterpret_cast<uint16_t*>(&y);
    return (uint32_t)xa | ((uint32_t)yb << 16);
}

// ---------------------------------------------------------------------------
// Mask decode (dtype sniffing)
// ---------------------------------------------------------------------------
__global__ void decode_mask_kernel(const unsigned char* __restrict__ mraw) {
    __shared__ int flags[2];
    const int t = threadIdx.x;
    if (t < 2) flags[t] = 0;
    __syncthreads();
    const unsigned char bch = mraw[t];
    if (((t & 3) == 3) && bch == 0x3F) atomicOr(&flags[0], 1);
    if (((t & 3) != 0) && bch != 0)    atomicOr(&flags[1], 1);
    __syncthreads();
    bool valid;
    if (flags[0])      valid = reinterpret_cast<const float*>(mraw)[t] != 0.0f;
    else if (flags[1]) valid = (bch != 0);
    else               valid = reinterpret_cast<const int*>(mraw)[t] != 0;
    g_maskAdd[t] = valid ? 0.0f : cfg::NEGINF;
}

// Merged input split: z=0 -> x, z=1 -> y
__global__ void conv_split2_kernel(const float* __restrict__ x, const float* __restrict__ y,
                                   __nv_bfloat16* __restrict__ xh, __nv_bfloat16* __restrict__ xl,
                                   __nv_bfloat16* __restrict__ yh, __nv_bfloat16* __restrict__ yl,
                                   int n) {
    const float* in = blockIdx.z ? y : x;
    __nv_bfloat16* hi = blockIdx.z ? yh : xh;
    __nv_bfloat16* lo = blockIdx.z ? yl : xl;
    for (int i = blockIdx.x * blockDim.x + threadIdx.x; i < n; i += gridDim.x * blockDim.x) {
        float v = in[i];
        __nv_bfloat16 h = __float2bfloat16(v);
        hi[i] = h;
        lo[i] = __float2bfloat16(v - __bfloat162float(h));
    }
}

// Merged weight transpose+split for Wq/Wk/Wv (z selects); Wp handled separately
__global__ void transconv3_kernel(const float* __restrict__ w0, const float* __restrict__ w1,
                                  const float* __restrict__ w2,
                                  __nv_bfloat16* __restrict__ h0, __nv_bfloat16* __restrict__ l0,
                                  __nv_bfloat16* __restrict__ h1, __nv_bfloat16* __restrict__ l1,
                                  __nv_bfloat16* __restrict__ h2, __nv_bfloat16* __restrict__ l2,
                                  int R, int C) {
    __shared__ float t[32][33];
    const int z = blockIdx.z;
    const float* in = (z == 0) ? w0 : (z == 1) ? w1 : w2;
    __nv_bfloat16* hi = (z == 0) ? h0 : (z == 1) ? h1 : h2;
    __nv_bfloat16* lo = (z == 0) ? l0 : (z == 1) ? l1 : l2;
    const int c0 = blockIdx.x * 32, r0 = blockIdx.y * 32;
    const int tx = threadIdx.x, ty = threadIdx.y;
#pragma unroll
    for (int i = 0; i < 32; i += 8)
        t[ty + i][tx] = in[(size_t)(r0 + ty + i) * C + c0 + tx];
    __syncthreads();
#pragma unroll
    for (int i = 0; i < 32; i += 8) {
        float v = t[tx][ty + i];
        __nv_bfloat16 h = __float2bfloat16(v);
        size_t o = (size_t)(c0 + ty + i) * R + r0 + tx;
        hi[o] = h;
        lo[o] = __float2bfloat16(v - __bfloat162float(h));
    }
}

__global__ void transconv_kernel(const float* __restrict__ in,
                                 __nv_bfloat16* __restrict__ hi,
                                 __nv_bfloat16* __restrict__ lo, int R, int C) {
    __shared__ float t[32][33];
    const int c0 = blockIdx.x * 32, r0 = blockIdx.y * 32;
    const int tx = threadIdx.x, ty = threadIdx.y;
#pragma unroll
    for (int i = 0; i < 32; i += 8)
        t[ty + i][tx] = in[(size_t)(r0 + ty + i) * C + c0 + tx];
    __syncthreads();
#pragma unroll
    for (int i = 0; i < 32; i += 8) {
        float v = t[tx][ty + i];
        __nv_bfloat16 h = __float2bfloat16(v);
        size_t o = (size_t)(c0 + ty + i) * R + r0 + tx;
        hi[o] = h;
        lo[o] = __float2bfloat16(v - __bfloat162float(h));
    }
}

// ---------------------------------------------------------------------------
// Row softmax fused with bf16 hi/lo split
// ---------------------------------------------------------------------------
__global__ void softmax_split_kernel(const float* __restrict__ E,
                                     __nv_bfloat16* __restrict__ hi,
                                     __nv_bfloat16* __restrict__ lo) {
    const size_t row = blockIdx.x;
    const float4* p = reinterpret_cast<const float4*>(E + row * cfg::SEQ);
    const int tid = threadIdx.x;
    float4 v = p[tid];
    __shared__ float red[8];

    float m = fmaxf(fmaxf(v.x, v.y), fmaxf(v.z, v.w));
#pragma unroll
    for (int o = 16; o > 0; o >>= 1) m = fmaxf(m, __shfl_xor_sync(0xffffffffu, m, o));
    if ((tid & 31) == 0) red[tid >> 5] = m;
    __syncthreads();
    if (tid == 0) {
        float mm = red[0];
#pragma unroll
        for (int i = 1; i < 8; i++) mm = fmaxf(mm, red[i]);
        red[0] = mm;
    }
    __syncthreads();
    m = red[0];
    __syncthreads();

    v.x = __expf(v.x - m); v.y = __expf(v.y - m);
    v.z = __expf(v.z - m); v.w = __expf(v.w - m);
    float s = v.x + v.y + v.z + v.w;
#pragma unroll
    for (int o = 16; o > 0; o >>= 1) s += __shfl_xor_sync(0xffffffffu, s, o);
    if ((tid & 31) == 0) red[tid >> 5] = s;
    __syncthreads();
    if (tid == 0) {
        float ss = red[0];
#pragma unroll
        for (int i = 1; i < 8; i++) ss += red[i];
        red[0] = ss;
    }
    __syncthreads();
    const float inv = 1.0f / red[0];
    v.x *= inv; v.y *= inv; v.z *= inv; v.w *= inv;

    float a[4] = {v.x, v.y, v.z, v.w};
    uint32_t hw[2], lw[2];
#pragma unroll
    for (int j = 0; j < 2; j++) {
        __nv_bfloat16 h0 = __float2bfloat16(a[2 * j]);
        __nv_bfloat16 h1 = __float2bfloat16(a[2 * j + 1]);
        float l0 = a[2 * j]     - __bfloat162float(h0);
        float l1 = a[2 * j + 1] - __bfloat162float(h1);
        uint16_t u0 = *reinterpret_cast<uint16_t*>(&h0);
        uint16_t u1 = *reinterpret_cast<uint16_t*>(&h1);
        hw[j] = (uint32_t)u0 | ((uint32_t)u1 << 16);
        lw[j] = pack_bf16(l0, l1);
    }
    const size_t o = row * cfg::SEQ + tid * 4;
    *reinterpret_cast<uint2*>(hi + o) = make_uint2(hw[0], hw[1]);
    *reinterpret_cast<uint2*>(lo + o) = make_uint2(lw[0], lw[1]);
}

// ===========================================================================
// K-major GEMM core: 256x128 CTA tile, 512 threads, 3-stage cp.async, K=512.
// `do3` gates the third emulation term (Ahi*Blo).
// ===========================================================================
constexpr int KSTRIDE = 80;
constexpr int PANA    = 256 * KSTRIDE;
constexpr int PANB    = 128 * KSTRIDE;
constexpr int KSTAGE  = 2 * PANA + 2 * PANB;
constexpr int KSMEM   = 3 * KSTAGE;

#define K_LOAD_STAGE(stage, ko)                                                   \
    do {                                                                          \
        const int _ar = tid >> 1, _ac = (ko) * 32 + (tid & 1) * 16;               \
        uint32_t _sa = sbase + (stage) * KSTAGE + _ar * KSTRIDE + (tid & 1) * 32; \
        cpasync16(_sa,          pAhi + (size_t)_ar * 512 + _ac);                  \
        cpasync16(_sa + 16,     pAhi + (size_t)_ar * 512 + _ac + 8);              \
        cpasync16(_sa + PANA,      pAlo + (size_t)_ar * 512 + _ac);               \
        cpasync16(_sa + PANA + 16, pAlo + (size_t)_ar * 512 + _ac + 8);           \
        const int _br = tid >> 2, _bc = (ko) * 32 + (tid & 3) * 8;                \
        uint32_t _sb = sbase + (stage) * KSTAGE + 2 * PANA + _br * KSTRIDE + (tid & 3) * 16; \
        cpasync16(_sb,        pBhi + (size_t)_br * 512 + _bc);                    \
        cpasync16(_sb + PANB, pBlo + (size_t)_br * 512 + _bc);                    \
        CP_COMMIT();                                                              \
    } while (0)

#define K_CORE_LOOP()                                                             \
    constexpr int NK = 16;                                                        \
    K_LOAD_STAGE(0, 0);                                                           \
    K_LOAD_STAGE(1, 1);                                                           \
    const int rA  = lane & 15;                                                    \
    const int kaA = ((lane & 16) >> 4) * 16;                                      \
    const int rB  = (lane & 7) + ((lane & 16) >> 1);                              \
    const int kbB = ((lane & 8) >> 3) * 16;                                       \
    int cs = 0, ns = 2;                                                           \
    for (int ko = 0; ko < NK; ko++) {                                             \
        if (ko + 1 < NK) { CP_WAIT(1); } else { CP_WAIT(0); }                     \
        __syncthreads();                                                          \
        if (ko + 2 < NK) { K_LOAD_STAGE(ns, ko + 2); }                            \
        const uint32_t st  = sbase + cs * KSTAGE;                                 \
        const uint32_t pAh = st, pAl = st + PANA;                                 \
        const uint32_t pBh = st + 2 * PANA, pBl = st + 2 * PANA + PANB;           \
        _Pragma("unroll")                                                         \
        for (int ks = 0; ks < 2; ks++) {                                          \
            const int kb = ks * 32;                                               \
            uint32_t ahi[2][4], alo[2][4];                                        \
            _Pragma("unroll")                                                     \
            for (int mi = 0; mi < 2; mi++) {                                      \
                const uint32_t offA = (uint32_t)((warpM + mi * 16 + rA) * KSTRIDE + kb + kaA); \
                LDSM4(ahi[mi][0], ahi[mi][1], ahi[mi][2], ahi[mi][3], pAh + offA);\
                LDSM4(alo[mi][0], alo[mi][1], alo[mi][2], alo[mi][3], pAl + offA);\
            }                                                                     \
            _Pragma("unroll")                                                     \
            for (int pr = 0; pr < 4; pr++) {                                      \
                uint32_t bh[2][2], bl[2][2];                                      \
                const uint32_t offB = (uint32_t)((warpN + pr * 16 + rB) * KSTRIDE + kb + kbB); \
                LDSM4(bh[0][0], bh[0][1], bh[1][0], bh[1][1], pBh + offB);        \
                LDSM4(bl[0][0], bl[0][1], bl[1][0], bl[1][1], pBl + offB);        \
                _Pragma("unroll")                                                 \
                for (int mi = 0; mi < 2; mi++)                                    \
                    _Pragma("unroll")                                             \
                    for (int nb = 0; nb < 2; nb++) {                              \
                        float* a4 = acc[mi][2 * pr + nb];                         \
                        MMA16816(a4, ahi[mi], bh[nb]);                            \
                        if (do3) { MMA16816(a4, ahi[mi], bl[nb]); }               \
                        MMA16816(a4, alo[mi], bh[nb]);                            \
                    }                                                             \
            }                                                                     \
        }                                                                         \
        cs = cs == 2 ? 0 : cs + 1;                                                \
        ns = ns == 2 ? 0 : ns + 1;                                                \
    }

// ---------------------------------------------------------------------------
// Merged QKV + xp projections. grid (32, 8, 4); z: 0=Q 1=K 2=V(2-term) 3=xp.
// ---------------------------------------------------------------------------
__global__ __launch_bounds__(512, 1)
void gemm_qkv(const __nv_bfloat16* __restrict__ xhi, const __nv_bfloat16* __restrict__ xlo,
              const __nv_bfloat16* __restrict__ yhi, const __nv_bfloat16* __restrict__ ylo,
              const __nv_bfloat16* __restrict__ wqh, const __nv_bfloat16* __restrict__ wql,
              const __nv_bfloat16* __restrict__ wkh, const __nv_bfloat16* __restrict__ wkl,
              const __nv_bfloat16* __restrict__ wvh, const __nv_bfloat16* __restrict__ wvl,
              const __nv_bfloat16* __restrict__ wph, const __nv_bfloat16* __restrict__ wpl,
              const float* __restrict__ bq, const float* __restrict__ bk,
              const float* __restrict__ bv,
              __nv_bfloat16* __restrict__ qhi, __nv_bfloat16* __restrict__ qlo,
              __nv_bfloat16* __restrict__ khi, __nv_bfloat16* __restrict__ klo,
              __nv_bfloat16* __restrict__ vhi,
              float* __restrict__ xp)
{
    extern __shared__ char dynraw[];
    const uint32_t sbase = smem_u32(dynraw);
    const int z = blockIdx.z;
    if (z == 3 && blockIdx.x >= 4) return;

    const int tid  = threadIdx.x;
    const int wid  = tid >> 5;
    const int lane = tid & 31;
    const int bm   = blockIdx.y * 256;
    const int bn   = blockIdx.x * 128;

    const __nv_bfloat16* pAhi = ((z == 1 || z == 2) ? yhi : xhi) + (size_t)bm * 512;
    const __nv_bfloat16* pAlo = ((z == 1 || z == 2) ? ylo : xlo) + (size_t)bm * 512;
    const __nv_bfloat16* pBhi = (z == 0 ? wqh : z == 1 ? wkh : z == 2 ? wvh : wph) + (size_t)bn * 512;
    const __nv_bfloat16* pBlo = (z == 0 ? wql : z == 1 ? wkl : z == 2 ? wvl : wpl) + (size_t)bn * 512;
    const float* bias = (z == 0 ? bq : z == 1 ? bk : bv);
    __nv_bfloat16* Chi = (z == 0 ? qhi : z == 1 ? khi : vhi);
    __nv_bfloat16* Clo = (z == 0 ? qlo : klo);   // unused for z==2

    const int warpM = (wid & 7) * 32;
    const int warpN = (wid >> 3) * 64;
    const bool do3 = (z != 2);    // V only needs bf16 accuracy: 2-term

    float acc[2][8][4];
#pragma unroll
    for (int i = 0; i < 2; i++)
#pragma unroll
        for (int j = 0; j < 8; j++)
#pragma unroll
            for (int q = 0; q < 4; q++) acc[i][j][q] = 0.0f;

    K_CORE_LOOP();

    const int gid = lane >> 2, tq = lane & 3;
#pragma unroll
    for (int mi = 0; mi < 2; mi++) {
#pragma unroll
        for (int h2 = 0; h2 < 2; h2++) {
            const int m = bm + warpM + mi * 16 + gid + h2 * 8;
#pragma unroll
            for (int nj = 0; nj < 8; nj++) {
                const int n = bn + warpN + nj * 8 + tq * 2;
                float v0 = acc[mi][nj][h2 * 2 + 0];
                float v1 = acc[mi][nj][h2 * 2 + 1];
                if (z < 3) {
                    v0 += bias[n]; v1 += bias[n + 1];
                    const int h = n >> 9, dd = n & 511;
                    const int b = m >> 10, s = m & 1023;
                    const size_t base = ((size_t)((h * 2 + b) * 1024 + s)) * 512 + dd;
                    __nv_bfloat16 h0 = __float2bfloat16(v0);
                    __nv_bfloat16 h1 = __float2bfloat16(v1);
                    uint16_t u0 = *reinterpret_cast<uint16_t*>(&h0);
                    uint16_t u1 = *reinterpret_cast<uint16_t*>(&h1);
                    *reinterpret_cast<uint32_t*>(Chi + base) = (uint32_t)u0 | ((uint32_t)u1 << 16);
                    if (z != 2) {
                        float l0 = v0 - __bfloat162float(h0);
                        float l1 = v1 - __bfloat162float(h1);
                        *reinterpret_cast<uint32_t*>(Clo + base) = pack_bf16(l0, l1);
                    }
                } else {
                    float* dst = xp + (size_t)m * 512 + n;
                    *reinterpret_cast<float2*>(dst) = make_float2(v0, v1);
                }
            }
        }
    }
}

// ---------------------------------------------------------------------------
// Energy: E[z] = Q[z] K[z]^T + mask (3-term). grid (8, 4, 16).
// ---------------------------------------------------------------------------
__global__ __launch_bounds__(512, 1)
void gemm_energy(const __nv_bfloat16* __restrict__ qhi, const __nv_bfloat16* __restrict__ qlo,
                 const __nv_bfloat16* __restrict__ khi, const __nv_bfloat16* __restrict__ klo,
                 float* __restrict__ E)
{
    extern __shared__ char dynraw[];
    const uint32_t sbase = smem_u32(dynraw);
    const int tid  = threadIdx.x;
    const int wid  = tid >> 5;
    const int lane = tid & 31;
    const int bm   = blockIdx.y * 256;
    const int bn   = blockIdx.x * 128;
    const int z    = blockIdx.z;

    const size_t sQK = (size_t)cfg::SEQ * cfg::DIM;
    const __nv_bfloat16* pAhi = qhi + z * sQK + (size_t)bm * 512;
    const __nv_bfloat16* pAlo = qlo + z * sQK + (size_t)bm * 512;
    const __nv_bfloat16* pBhi = khi + z * sQK + (size_t)bn * 512;
    const __nv_bfloat16* pBlo = klo + z * sQK + (size_t)bn * 512;

    const int warpM = (wid & 7) * 32;
    const int warpN = (wid >> 3) * 64;
    constexpr bool do3 = true;

    float acc[2][8][4];
#pragma unroll
    for (int i = 0; i < 2; i++)
#pragma unroll
        for (int j = 0; j < 8; j++)
#pragma unroll
            for (int q = 0; q < 4; q++) acc[i][j][q] = 0.0f;

    K_CORE_LOOP();

    const int gid = lane >> 2, tq = lane & 3;
#pragma unroll
    for (int mi = 0; mi < 2; mi++) {
#pragma unroll
        for (int h2 = 0; h2 < 2; h2++) {
            const int m = bm + warpM + mi * 16 + gid + h2 * 8;
#pragma unroll
            for (int nj = 0; nj < 8; nj++) {
                const int n = bn + warpN + nj * 8 + tq * 2;
                float* dst = E + (size_t)z * cfg::SEQ * cfg::SEQ + (size_t)m * cfg::SEQ + n;
                *reinterpret_cast<float2*>(dst) = make_float2(
                    acc[mi][nj][h2 * 2 + 0] + g_maskAdd[n],
                    acc[mi][nj][h2 * 2 + 1] + g_maskAdd[n + 1]);
            }
        }
    }
}

// ---------------------------------------------------------------------------
// AV: out[z,t,dv] = sum_s attn[z,s,t] * V[z,s,dv], 2-term (attn hi+lo, V hi).
// 256(t)x128(dv) tile, 512 threads, 3 stages, trans-ldmatrix. grid (4,4,16).
// ---------------------------------------------------------------------------
constexpr int AV_SA   = 528;
constexpr int AV_SB   = 272;
constexpr int AVPANA  = 32 * AV_SA;               // 16896
constexpr int AVPANB  = 32 * AV_SB;               // 8704
constexpr int AVSTAGE = 2 * AVPANA + AVPANB;      // 42496 (no V-lo panel)
constexpr int AVSMEM  = 3 * AVSTAGE;              // 127488

__global__ __launch_bounds__(512, 1)
void gemm_av(const __nv_bfloat16* __restrict__ Ahi, const __nv_bfloat16* __restrict__ Alo,
             const __nv_bfloat16* __restrict__ Bhi,
             float* __restrict__ out, const float* __restrict__ gamma)
{
    extern __shared__ char dynraw[];
    const uint32_t sbase = smem_u32(dynraw);
    const int tid  = threadIdx.x;
    const int wid  = tid >> 5;
    const int lane = tid & 31;
    const int bm   = blockIdx.y * 256;   // t
    const int bn   = blockIdx.x * 128;   // dv
    const int z    = blockIdx.z;

    const size_t sA = (size_t)1024 * 1024, sB = (size_t)1024 * 512;
    const __nv_bfloat16* pAhi = Ahi + z * sA + bm;
    const __nv_bfloat16* pAlo = Alo + z * sA + bm;
    const __nv_bfloat16* pBhi = Bhi + z * sB + bn;

    const int warpM = (wid & 7) * 32;
    const int warpN = (wid >> 3) * 64;

    float acc[2][8][4];
#pragma unroll
    for (int i = 0; i < 2; i++)
#pragma unroll
        for (int j = 0; j < 8; j++)
#pragma unroll
            for (int q = 0; q < 4; q++) acc[i][j][q] = 0.0f;

    constexpr int NK = 32;

    const int ar = tid >> 4, abyte = (tid & 15) * 32;
    const int bbyte = (tid & 15) * 16;

#define AV_LOAD_STAGE(stage, ko)                                                   \
    do {                                                                           \
        const int _k = (ko) * 32 + ar;                                             \
        uint32_t _sa = sbase + (stage) * AVSTAGE + ar * AV_SA + abyte;             \
        cpasync16(_sa,      pAhi + (size_t)_k * 1024 + abyte / 2);                 \
        cpasync16(_sa + 16, pAhi + (size_t)_k * 1024 + abyte / 2 + 8);             \
        cpasync16(_sa + AVPANA,      pAlo + (size_t)_k * 1024 + abyte / 2);        \
        cpasync16(_sa + AVPANA + 16, pAlo + (size_t)_k * 1024 + abyte / 2 + 8);    \
        uint32_t _sb = sbase + (stage) * AVSTAGE + 2 * AVPANA + ar * AV_SB + bbyte;\
        cpasync16(_sb, pBhi + (size_t)_k * 512 + bbyte / 2);                       \
        CP_COMMIT();                                                               \
    } while (0)

    AV_LOAD_STAGE(0, 0);
    AV_LOAD_STAGE(1, 1);

    const int rAk = (lane & 7) + ((lane >> 4) & 1) * 8;
    const int cAm = ((lane >> 3) & 1) * 8;
    const int rBk = (lane & 7) + ((lane >> 3) & 1) * 8;
    const int cBn = ((lane >> 4) & 1) * 8;

    int cs = 0, ns = 2;
    for (int ko = 0; ko < NK; ko++) {
        if (ko + 1 < NK) { CP_WAIT(1); } else { CP_WAIT(0); }
        __syncthreads();
        if (ko + 2 < NK) { AV_LOAD_STAGE(ns, ko + 2); }

        const uint32_t st  = sbase + cs * AVSTAGE;
        const uint32_t pAh = st, pAl = st + AVPANA;
        const uint32_t pBh = st + 2 * AVPANA;

#pragma unroll
        for (int ks = 0; ks < 2; ks++) {
            uint32_t ahi[2][4], alo[2][4];
#pragma unroll
            for (int mi = 0; mi < 2; mi++) {
                const uint32_t offA =
                    (uint32_t)((ks * 16 + rAk) * AV_SA + (warpM + mi * 16 + cAm) * 2);
                LDSM4T(ahi[mi][0], ahi[mi][1], ahi[mi][2], ahi[mi][3], pAh + offA);
                LDSM4T(alo[mi][0], alo[mi][1], alo[mi][2], alo[mi][3], pAl + offA);
            }
#pragma unroll
            for (int pr = 0; pr < 4; pr++) {
                uint32_t bh[2][2];
                const uint32_t offB =
                    (uint32_t)((ks * 16 + rBk) * AV_SB + (warpN + pr * 16 + cBn) * 2);
                LDSM4T(bh[0][0], bh[0][1], bh[1][0], bh[1][1], pBh + offB);
#pragma unroll
                for (int mi = 0; mi < 2; mi++)
#pragma unroll
                    for (int nb = 0; nb < 2; nb++) {
                        float* a4 = acc[mi][2 * pr + nb];
                        MMA16816(a4, ahi[mi], bh[nb]);
                        MMA16816(a4, alo[mi], bh[nb]);
                    }
            }
        }
        cs = cs == 2 ? 0 : cs + 1;
        ns = ns == 2 ? 0 : ns + 1;
    }

    const int gid = lane >> 2, tq = lane & 3;
    const int h = z >> 1, b = z & 1;
    const float g = gamma[h];
    const float inv = 1.0f / (g + 1.0f);
#pragma unroll
    for (int mi = 0; mi < 2; mi++) {
#pragma unroll
        for (int h2 = 0; h2 < 2; h2++) {
            const int m = bm + warpM + mi * 16 + gid + h2 * 8;
#pragma unroll
            for (int nj = 0; nj < 8; nj++) {
                const int n = bn + warpN + nj * 8 + tq * 2;
                float v0 = acc[mi][nj][h2 * 2 + 0];
                float v1 = acc[mi][nj][h2 * 2 + 1];
                const float2 x2 = *reinterpret_cast<const float2*>(
                    g_XP + ((size_t)(b * 1024 + m)) * 512 + n);
                float* dst = out + ((size_t)((b * 8 + h) * 1024 + m)) * 512 + n;
                *reinterpret_cast<float2*>(dst) =
                    make_float2((g * v0 + x2.x) * inv, (g * v1 + x2.y) * inv);
            }
        }
    }
}

// ---------------------------------------------------------------------------
// Launcher
// ---------------------------------------------------------------------------
extern "C" void kernel_launch(void* const* d_in, const int* in_sizes, int n_in,
                              void* d_out, int out_size) {
    using namespace cfg;
    const float* x     = (const float*)d_in[0];
    const float* y     = (const float*)d_in[1];
    const float* Wq    = (const float*)d_in[2];
    const float* bq    = (const float*)d_in[3];
    const float* Wk    = (const float*)d_in[4];
    const float* bk    = (const float*)d_in[5];
    const float* Wv    = (const float*)d_in[6];
    const float* bv    = (const float*)d_in[7];
    const float* Wp    = (const float*)d_in[8];
    const float* gamma = (const float*)d_in[9];
    const unsigned char* mask = (const unsigned char*)d_in[10];
    float* out = (float*)d_out;

    __nv_bfloat16 *xhi, *xlo, *wqh, *wql, *wkh, *wkl, *wvh, *wvl, *wph, *wpl;
    __nv_bfloat16 *qhi, *qlo, *khi, *klo, *vhi, *ahi, *alo;
    float *pE, *pXP;
    cudaGetSymbolAddress((void**)&xhi, g_xhi);    cudaGetSymbolAddress((void**)&xlo, g_xlo);
    cudaGetSymbolAddress((void**)&wqh, g_Wqt_hi); cudaGetSymbolAddress((void**)&wql, g_Wqt_lo);
    cudaGetSymbolAddress((void**)&wkh, g_Wkt_hi); cudaGetSymbolAddress((void**)&wkl, g_Wkt_lo);
    cudaGetSymbolAddress((void**)&wvh, g_Wvt_hi); cudaGetSymbolAddress((void**)&wvl, g_Wvt_lo);
    cudaGetSymbolAddress((void**)&wph, g_Wpt_hi); cudaGetSymbolAddress((void**)&wpl, g_Wpt_lo);
    cudaGetSymbolAddress((void**)&qhi, g_Qhi);    cudaGetSymbolAddress((void**)&qlo, g_Qlo);
    cudaGetSymbolAddress((void**)&khi, g_Khi);    cudaGetSymbolAddress((void**)&klo, g_Klo);
    cudaGetSymbolAddress((void**)&vhi, g_Vhi);
    cudaGetSymbolAddress((void**)&pE,  g_E);
    cudaGetSymbolAddress((void**)&ahi, g_Ahi);    cudaGetSymbolAddress((void**)&alo, g_Alo);
    cudaGetSymbolAddress((void**)&pXP, g_XP);

    cudaFuncSetAttribute(gemm_qkv,    cudaFuncAttributeMaxDynamicSharedMemorySize, KSMEM);
    cudaFuncSetAttribute(gemm_energy, cudaFuncAttributeMaxDynamicSharedMemorySize, KSMEM);
    cudaFuncSetAttribute(gemm_av,     cudaFuncAttributeMaxDynamicSharedMemorySize, AVSMEM);

    decode_mask_kernel<<<1, 1024>>>(mask);

    // x -> xhi/xlo; y -> g_Ahi/g_Alo (temp reuse; attn overwrites later)
    conv_split2_kernel<<<dim3(512, 1, 2), 256>>>(x, y, xhi, xlo, ahi, alo, 2048 * 512);

    transconv3_kernel<<<dim3(128, 16, 3), dim3(32, 8)>>>(Wq, Wk, Wv,
                                                         wqh, wql, wkh, wkl, wvh, wvl,
                                                         512, 4096);
    transconv_kernel<<<dim3(16, 16, 1), dim3(32, 8)>>>(Wp, wph, wpl, 512, 512);

    // Merged Q/K/V/xp projections (V is 2-term)
    gemm_qkv<<<dim3(32, 8, 4), 512, KSMEM>>>(xhi, xlo, ahi, alo,
                                             wqh, wql, wkh, wkl, wvh, wvl, wph, wpl,
                                             bq, bk, bv,
                                             qhi, qlo, khi, klo, vhi, pXP);

    // Energy + mask
    gemm_energy<<<dim3(8, 4, HB), 512, KSMEM>>>(qhi, qlo, khi, klo, pE);

    // softmax + bf16 split (overwrites the y-split scratch with attn)
    softmax_split_kernel<<<HB * SEQ, 256>>>(pE, ahi, alo);

    // AV (2-term) + blend
    gemm_av<<<dim3(4, 4, HB), 512, AVSMEM>>>(ahi, alo, vhi, out, gamma);

    (void)in_sizes; (void)n_in; (void)out_size;
}

// round 11
// speedup vs baseline: 2.7924x; 1.0072x over previous
#include <cuda_runtime.h>
#include <cuda_fp16.h>
#include <cstdint>

namespace cfg {
constexpr int BATCH = 2;
constexpr int SEQ   = 1024;
constexpr int DIM   = 512;
constexpr int HEADS = 8;
constexpr int HB    = HEADS * BATCH;
constexpr float NEGINF = -1e30f;
}

// ---------------------------------------------------------------------------
// Device scratch (fp16 hi/lo split representation)
// ---------------------------------------------------------------------------
__device__ __half g_xhi [2048 * 512], g_xlo [2048 * 512];
__device__ __half g_Wqt_hi[4096 * 512], g_Wqt_lo[4096 * 512];
__device__ __half g_Wkt_hi[4096 * 512], g_Wkt_lo[4096 * 512];
__device__ __half g_Wvt_hi[4096 * 512], g_Wvt_lo[4096 * 512];
__device__ __half g_Wpt_hi[512 * 512],  g_Wpt_lo[512 * 512];
__device__ __half g_Qhi[(size_t)16 * 1024 * 512], g_Qlo[(size_t)16 * 1024 * 512];
__device__ __half g_Khi[(size_t)16 * 1024 * 512], g_Klo[(size_t)16 * 1024 * 512];
__device__ __half g_Vhi[(size_t)16 * 1024 * 512], g_Vlo[(size_t)16 * 1024 * 512];
__device__ float  g_E  [(size_t)16 * 1024 * 1024];
__device__ __half g_Ahi[(size_t)16 * 1024 * 1024];   // attn (single fp16)
__device__ __half g_Ylo[(size_t)2048 * 512];          // y lo (proj input only)
__device__ float  g_XP [2048 * 512];
__device__ float  g_maskAdd[cfg::SEQ];

// ---------------------------------------------------------------------------
// PTX helpers — stable (non-"a") instructions only
// ---------------------------------------------------------------------------
__device__ __forceinline__ uint32_t smem_u32(const void* p) {
    uint32_t a;
    asm("{ .reg .u64 t; cvta.to.shared.u64 t, %1; cvt.u32.u64 %0, t; }" : "=r"(a) : "l"(p));
    return a;
}
__device__ __forceinline__ void cpasync16(uint32_t s, const void* g) {
    asm volatile("cp.async.cg.shared.global [%0], [%1], 16;" :: "r"(s), "l"(g));
}
#define CP_COMMIT()  asm volatile("cp.async.commit_group;" ::: "memory")
#define CP_WAIT(n)   asm volatile("cp.async.wait_group %0;" :: "n"(n) : "memory")
#define LDSM4(r0, r1, r2, r3, a) \
    asm volatile("ldmatrix.sync.aligned.m8n8.x4.shared.b16 {%0,%1,%2,%3}, [%4];" \
        : "=r"(r0), "=r"(r1), "=r"(r2), "=r"(r3) : "r"(a))
#define LDSM4T(r0, r1, r2, r3, a) \
    asm volatile("ldmatrix.sync.aligned.m8n8.x4.trans.shared.b16 {%0,%1,%2,%3}, [%4];" \
        : "=r"(r0), "=r"(r1), "=r"(r2), "=r"(r3) : "r"(a))
#define MMA16816(c, a, b) \
    asm volatile("mma.sync.aligned.m16n8k16.row.col.f32.f16.f16.f32 " \
        "{%0,%1,%2,%3}, {%4,%5,%6,%7}, {%8,%9}, {%0,%1,%2,%3};" \
        : "+f"((c)[0]), "+f"((c)[1]), "+f"((c)[2]), "+f"((c)[3]) \
        : "r"((a)[0]), "r"((a)[1]), "r"((a)[2]), "r"((a)[3]), "r"((b)[0]), "r"((b)[1]))

__device__ __forceinline__ uint32_t pack_f16(float a, float b) {
    __half2 h = __floats2half2_rn(a, b);
    return *reinterpret_cast<uint32_t*>(&h);
}

// ---------------------------------------------------------------------------
// Mask decode (dtype sniffing)
// ---------------------------------------------------------------------------
__global__ void decode_mask_kernel(const unsigned char* __restrict__ mraw) {
    __shared__ int flags[2];
    const int t = threadIdx.x;
    if (t < 2) flags[t] = 0;
    __syncthreads();
    const unsigned char bch = mraw[t];
    if (((t & 3) == 3) && bch == 0x3F) atomicOr(&flags[0], 1);
    if (((t & 3) != 0) && bch != 0)    atomicOr(&flags[1], 1);
    __syncthreads();
    bool valid;
    if (flags[0])      valid = reinterpret_cast<const float*>(mraw)[t] != 0.0f;
    else if (flags[1]) valid = (bch != 0);
    else               valid = reinterpret_cast<const int*>(mraw)[t] != 0;
    g_maskAdd[t] = valid ? 0.0f : cfg::NEGINF;
}

// Merged input split: z=0 -> x, z=1 -> y
__global__ void conv_split2_kernel(const float* __restrict__ x, const float* __restrict__ y,
                                   __half* __restrict__ xh, __half* __restrict__ xl,
                                   __half* __restrict__ yh, __half* __restrict__ yl,
                                   int n) {
    const float* in = blockIdx.z ? y : x;
    __half* hi = blockIdx.z ? yh : xh;
    __half* lo = blockIdx.z ? yl : xl;
    for (int i = blockIdx.x * blockDim.x + threadIdx.x; i < n; i += gridDim.x * blockDim.x) {
        float v = in[i];
        __half h = __float2half_rn(v);
        hi[i] = h;
        lo[i] = __float2half_rn(v - __half2float(h));
    }
}

// Merged weight transpose+split: z=0..2 -> Wq/Wk/Wv (512x4096), z=3 -> Wp (512x512)
__global__ void transconv4_kernel(const float* __restrict__ w0, const float* __restrict__ w1,
                                  const float* __restrict__ w2, const float* __restrict__ w3,
                                  __half* __restrict__ h0, __half* __restrict__ l0,
                                  __half* __restrict__ h1, __half* __restrict__ l1,
                                  __half* __restrict__ h2, __half* __restrict__ l2,
                                  __half* __restrict__ h3, __half* __restrict__ l3) {
    const int z = blockIdx.z;
    const int C = (z == 3) ? 512 : 4096;
    if (blockIdx.x * 32 >= C) return;
    const int R = 512;
    const float* in = (z == 0) ? w0 : (z == 1) ? w1 : (z == 2) ? w2 : w3;
    __half* hi = (z == 0) ? h0 : (z == 1) ? h1 : (z == 2) ? h2 : h3;
    __half* lo = (z == 0) ? l0 : (z == 1) ? l1 : (z == 2) ? l2 : l3;
    __shared__ float t[32][33];
    const int c0 = blockIdx.x * 32, r0 = blockIdx.y * 32;
    const int tx = threadIdx.x, ty = threadIdx.y;
#pragma unroll
    for (int i = 0; i < 32; i += 8)
        t[ty + i][tx] = in[(size_t)(r0 + ty + i) * C + c0 + tx];
    __syncthreads();
#pragma unroll
    for (int i = 0; i < 32; i += 8) {
        float v = t[tx][ty + i];
        __half h = __float2half_rn(v);
        size_t o = (size_t)(c0 + ty + i) * R + r0 + tx;
        hi[o] = h;
        lo[o] = __float2half_rn(v - __half2float(h));
    }
}

// ---------------------------------------------------------------------------
// Row softmax -> attn fp16 (single precision-level output)
// ---------------------------------------------------------------------------
__global__ void softmax_split_kernel(const float* __restrict__ E,
                                     __half* __restrict__ hi) {
    const size_t row = blockIdx.x;
    const float4* p = reinterpret_cast<const float4*>(E + row * cfg::SEQ);
    const int tid = threadIdx.x;
    float4 v = p[tid];
    __shared__ float red[8];

    float m = fmaxf(fmaxf(v.x, v.y), fmaxf(v.z, v.w));
#pragma unroll
    for (int o = 16; o > 0; o >>= 1) m = fmaxf(m, __shfl_xor_sync(0xffffffffu, m, o));
    if ((tid & 31) == 0) red[tid >> 5] = m;
    __syncthreads();
    if (tid == 0) {
        float mm = red[0];
#pragma unroll
        for (int i = 1; i < 8; i++) mm = fmaxf(mm, red[i]);
        red[0] = mm;
    }
    __syncthreads();
    m = red[0];
    __syncthreads();

    v.x = __expf(v.x - m); v.y = __expf(v.y - m);
    v.z = __expf(v.z - m); v.w = __expf(v.w - m);
    float s = v.x + v.y + v.z + v.w;
#pragma unroll
    for (int o = 16; o > 0; o >>= 1) s += __shfl_xor_sync(0xffffffffu, s, o);
    if ((tid & 31) == 0) red[tid >> 5] = s;
    __syncthreads();
    if (tid == 0) {
        float ss = red[0];
#pragma unroll
        for (int i = 1; i < 8; i++) ss += red[i];
        red[0] = ss;
    }
    __syncthreads();
    const float inv = 1.0f / red[0];

    uint32_t hw0 = pack_f16(v.x * inv, v.y * inv);
    uint32_t hw1 = pack_f16(v.z * inv, v.w * inv);
    const size_t o = row * cfg::SEQ + tid * 4;
    *reinterpret_cast<uint2*>(hi + o) = make_uint2(hw0, hw1);
}

// ===========================================================================
// K-major GEMM core: 256x128 CTA tile, 512 threads, 3-stage cp.async, K=512.
// `do3` gates the third emulation term (Ahi*Blo).
// ===========================================================================
constexpr int KSTRIDE = 80;
constexpr int PANA    = 256 * KSTRIDE;
constexpr int PANB    = 128 * KSTRIDE;
constexpr int KSTAGE  = 2 * PANA + 2 * PANB;
constexpr int KSMEM   = 3 * KSTAGE;

#define K_LOAD_STAGE(stage, ko)                                                   \
    do {                                                                          \
        const int _ar = tid >> 1, _ac = (ko) * 32 + (tid & 1) * 16;               \
        uint32_t _sa = sbase + (stage) * KSTAGE + _ar * KSTRIDE + (tid & 1) * 32; \
        cpasync16(_sa,          pAhi + (size_t)_ar * 512 + _ac);                  \
        cpasync16(_sa + 16,     pAhi + (size_t)_ar * 512 + _ac + 8);              \
        cpasync16(_sa + PANA,      pAlo + (size_t)_ar * 512 + _ac);               \
        cpasync16(_sa + PANA + 16, pAlo + (size_t)_ar * 512 + _ac + 8);           \
        const int _br = tid >> 2, _bc = (ko) * 32 + (tid & 3) * 8;                \
        uint32_t _sb = sbase + (stage) * KSTAGE + 2 * PANA + _br * KSTRIDE + (tid & 3) * 16; \
        cpasync16(_sb,        pBhi + (size_t)_br * 512 + _bc);                    \
        cpasync16(_sb + PANB, pBlo + (size_t)_br * 512 + _bc);                    \
        CP_COMMIT();                                                              \
    } while (0)

#define K_CORE_LOOP()                                                             \
    constexpr int NK = 16;                                                        \
    K_LOAD_STAGE(0, 0);                                                           \
    K_LOAD_STAGE(1, 1);                                                           \
    const int rA  = lane & 15;                                                    \
    const int kaA = ((lane & 16) >> 4) * 16;                                      \
    const int rB  = (lane & 7) + ((lane & 16) >> 1);                              \
    const int kbB = ((lane & 8) >> 3) * 16;                                       \
    int cs = 0, ns = 2;                                                           \
    for (int ko = 0; ko < NK; ko++) {                                             \
        if (ko + 1 < NK) { CP_WAIT(1); } else { CP_WAIT(0); }                     \
        __syncthreads();                                                          \
        if (ko + 2 < NK) { K_LOAD_STAGE(ns, ko + 2); }                            \
        const uint32_t st  = sbase + cs * KSTAGE;                                 \
        const uint32_t pAh = st, pAl = st + PANA;                                 \
        const uint32_t pBh = st + 2 * PANA, pBl = st + 2 * PANA + PANB;           \
        _Pragma("unroll")                                                         \
        for (int ks = 0; ks < 2; ks++) {                                          \
            const int kb = ks * 32;                                               \
            uint32_t ahi[2][4], alo[2][4];                                        \
            _Pragma("unroll")                                                     \
            for (int mi = 0; mi < 2; mi++) {                                      \
                const uint32_t offA = (uint32_t)((warpM + mi * 16 + rA) * KSTRIDE + kb + kaA); \
                LDSM4(ahi[mi][0], ahi[mi][1], ahi[mi][2], ahi[mi][3], pAh + offA);\
                LDSM4(alo[mi][0], alo[mi][1], alo[mi][2], alo[mi][3], pAl + offA);\
            }                                                                     \
            _Pragma("unroll")                                                     \
            for (int pr = 0; pr < 4; pr++) {                                      \
                uint32_t bh[2][2], bl[2][2];                                      \
                const uint32_t offB = (uint32_t)((warpN + pr * 16 + rB) * KSTRIDE + kb + kbB); \
                LDSM4(bh[0][0], bh[0][1], bh[1][0], bh[1][1], pBh + offB);        \
                LDSM4(bl[0][0], bl[0][1], bl[1][0], bl[1][1], pBl + offB);        \
                _Pragma("unroll")                                                 \
                for (int mi = 0; mi < 2; mi++)                                    \
                    _Pragma("unroll")                                             \
                    for (int nb = 0; nb < 2; nb++) {                              \
                        float* a4 = acc[mi][2 * pr + nb];                         \
                        MMA16816(a4, ahi[mi], bh[nb]);                            \
                        if (do3) { MMA16816(a4, ahi[mi], bl[nb]); }               \
                        MMA16816(a4, alo[mi], bh[nb]);                            \
                    }                                                             \
            }                                                                     \
        }                                                                         \
        cs = cs == 2 ? 0 : cs + 1;                                                \
        ns = ns == 2 ? 0 : ns + 1;                                                \
    }

// ---------------------------------------------------------------------------
// Merged QKV + xp projections. grid (32, 8, 4); z: 0=Q 1=K 2=V(2-term) 3=xp.
// Q/K/V epilogues store fp16 hi/lo pairs with head relayout.
// ---------------------------------------------------------------------------
__global__ __launch_bounds__(512, 1)
void gemm_qkv(const __half* __restrict__ xhi, const __half* __restrict__ xlo,
              const __half* __restrict__ yhi, const __half* __restrict__ ylo,
              const __half* __restrict__ wqh, const __half* __restrict__ wql,
              const __half* __restrict__ wkh, const __half* __restrict__ wkl,
              const __half* __restrict__ wvh, const __half* __restrict__ wvl,
              const __half* __restrict__ wph, const __half* __restrict__ wpl,
              const float* __restrict__ bq, const float* __restrict__ bk,
              const float* __restrict__ bv,
              __half* __restrict__ qhi, __half* __restrict__ qlo,
              __half* __restrict__ khi, __half* __restrict__ klo,
              __half* __restrict__ vhi, __half* __restrict__ vlo,
              float* __restrict__ xp)
{
    extern __shared__ char dynraw[];
    const uint32_t sbase = smem_u32(dynraw);
    const int z = blockIdx.z;
    if (z == 3 && blockIdx.x >= 4) return;

    const int tid  = threadIdx.x;
    const int wid  = tid >> 5;
    const int lane = tid & 31;
    const int bm   = blockIdx.y * 256;
    const int bn   = blockIdx.x * 128;

    const __half* pAhi = ((z == 1 || z == 2) ? yhi : xhi) + (size_t)bm * 512;
    const __half* pAlo = ((z == 1 || z == 2) ? ylo : xlo) + (size_t)bm * 512;
    const __half* pBhi = (z == 0 ? wqh : z == 1 ? wkh : z == 2 ? wvh : wph) + (size_t)bn * 512;
    const __half* pBlo = (z == 0 ? wql : z == 1 ? wkl : z == 2 ? wvl : wpl) + (size_t)bn * 512;
    const float* bias = (z == 0 ? bq : z == 1 ? bk : bv);
    __half* Chi = (z == 0 ? qhi : z == 1 ? khi : vhi);
    __half* Clo = (z == 0 ? qlo : z == 1 ? klo : vlo);

    const int warpM = (wid & 7) * 32;
    const int warpN = (wid >> 3) * 64;
    const bool do3 = (z != 2);    // V: 2-term (fp16 -> error ~2^-12)

    float acc[2][8][4];
#pragma unroll
    for (int i = 0; i < 2; i++)
#pragma unroll
        for (int j = 0; j < 8; j++)
#pragma unroll
            for (int q = 0; q < 4; q++) acc[i][j][q] = 0.0f;

    K_CORE_LOOP();

    const int gid = lane >> 2, tq = lane & 3;
#pragma unroll
    for (int mi = 0; mi < 2; mi++) {
#pragma unroll
        for (int h2 = 0; h2 < 2; h2++) {
            const int m = bm + warpM + mi * 16 + gid + h2 * 8;
#pragma unroll
            for (int nj = 0; nj < 8; nj++) {
                const int n = bn + warpN + nj * 8 + tq * 2;
                float v0 = acc[mi][nj][h2 * 2 + 0];
                float v1 = acc[mi][nj][h2 * 2 + 1];
                if (z < 3) {
                    v0 += bias[n]; v1 += bias[n + 1];
                    const int h = n >> 9, dd = n & 511;
                    const int b = m >> 10, s = m & 1023;
                    const size_t base = ((size_t)((h * 2 + b) * 1024 + s)) * 512 + dd;
                    __half h0 = __float2half_rn(v0);
                    __half h1 = __float2half_rn(v1);
                    float l0 = v0 - __half2float(h0);
                    float l1 = v1 - __half2float(h1);
                    __half2 hp = __halves2half2(h0, h1);
                    *reinterpret_cast<uint32_t*>(Chi + base) = *reinterpret_cast<uint32_t*>(&hp);
                    *reinterpret_cast<uint32_t*>(Clo + base) = pack_f16(l0, l1);
                } else {
                    float* dst = xp + (size_t)m * 512 + n;
                    *reinterpret_cast<float2*>(dst) = make_float2(v0, v1);
                }
            }
        }
    }
}

// ---------------------------------------------------------------------------
// Energy: E[z] = Q[z] K[z]^T + mask (3-term). grid (8, 4, 16).
// ---------------------------------------------------------------------------
__global__ __launch_bounds__(512, 1)
void gemm_energy(const __half* __restrict__ qhi, const __half* __restrict__ qlo,
                 const __half* __restrict__ khi, const __half* __restrict__ klo,
                 float* __restrict__ E)
{
    extern __shared__ char dynraw[];
    const uint32_t sbase = smem_u32(dynraw);
    const int tid  = threadIdx.x;
    const int wid  = tid >> 5;
    const int lane = tid & 31;
    const int bm   = blockIdx.y * 256;
    const int bn   = blockIdx.x * 128;
    const int z    = blockIdx.z;

    const size_t sQK = (size_t)cfg::SEQ * cfg::DIM;
    const __half* pAhi = qhi + z * sQK + (size_t)bm * 512;
    const __half* pAlo = qlo + z * sQK + (size_t)bm * 512;
    const __half* pBhi = khi + z * sQK + (size_t)bn * 512;
    const __half* pBlo = klo + z * sQK + (size_t)bn * 512;

    const int warpM = (wid & 7) * 32;
    const int warpN = (wid >> 3) * 64;
    constexpr bool do3 = true;

    float acc[2][8][4];
#pragma unroll
    for (int i = 0; i < 2; i++)
#pragma unroll
        for (int j = 0; j < 8; j++)
#pragma unroll
            for (int q = 0; q < 4; q++) acc[i][j][q] = 0.0f;

    K_CORE_LOOP();

    const int gid = lane >> 2, tq = lane & 3;
#pragma unroll
    for (int mi = 0; mi < 2; mi++) {
#pragma unroll
        for (int h2 = 0; h2 < 2; h2++) {
            const int m = bm + warpM + mi * 16 + gid + h2 * 8;
#pragma unroll
            for (int nj = 0; nj < 8; nj++) {
                const int n = bn + warpN + nj * 8 + tq * 2;
                float* dst = E + (size_t)z * cfg::SEQ * cfg::SEQ + (size_t)m * cfg::SEQ + n;
                *reinterpret_cast<float2*>(dst) = make_float2(
                    acc[mi][nj][h2 * 2 + 0] + g_maskAdd[n],
                    acc[mi][nj][h2 * 2 + 1] + g_maskAdd[n + 1]);
            }
        }
    }
}

// ---------------------------------------------------------------------------
// AV: out[z,t,dv] = sum_s attn[z,s,t] * (Vhi + Vlo)[z,s,dv]  (2 MMAs/term-pair)
// 256(t)x128(dv) tile, 512 threads, 3 stages, trans-ldmatrix. grid (4,4,16).
// ---------------------------------------------------------------------------
constexpr int AV_SA   = 528;
constexpr int AV_SB   = 272;
constexpr int AVPANA  = 32 * AV_SA;               // attn hi: 16896
constexpr int AVPANB  = 32 * AV_SB;               // V hi / V lo: 8704 each
constexpr int AVSTAGE = AVPANA + 2 * AVPANB;      // 34304
constexpr int AVSMEM  = 3 * AVSTAGE;              // 102912

__global__ __launch_bounds__(512, 1)
void gemm_av(const __half* __restrict__ Ahi,
             const __half* __restrict__ Bhi, const __half* __restrict__ Blo,
             float* __restrict__ out, const float* __restrict__ gamma)
{
    extern __shared__ char dynraw[];
    const uint32_t sbase = smem_u32(dynraw);
    const int tid  = threadIdx.x;
    const int wid  = tid >> 5;
    const int lane = tid & 31;
    const int bm   = blockIdx.y * 256;   // t
    const int bn   = blockIdx.x * 128;   // dv
    const int z    = blockIdx.z;

    const size_t sA = (size_t)1024 * 1024, sB = (size_t)1024 * 512;
    const __half* pAhi = Ahi + z * sA + bm;
    const __half* pBhi = Bhi + z * sB + bn;
    const __half* pBlo = Blo + z * sB + bn;

    const int warpM = (wid & 7) * 32;
    const int warpN = (wid >> 3) * 64;

    float acc[2][8][4];
#pragma unroll
    for (int i = 0; i < 2; i++)
#pragma unroll
        for (int j = 0; j < 8; j++)
#pragma unroll
            for (int q = 0; q < 4; q++) acc[i][j][q] = 0.0f;

    constexpr int NK = 32;

    const int ar = tid >> 4, abyte = (tid & 15) * 32;
    const int bbyte = (tid & 15) * 16;

#define AV_LOAD_STAGE(stage, ko)                                                   \
    do {                                                                           \
        const int _k = (ko) * 32 + ar;                                             \
        uint32_t _sa = sbase + (stage) * AVSTAGE + ar * AV_SA + abyte;             \
        cpasync16(_sa,      pAhi + (size_t)_k * 1024 + abyte / 2);                 \
        cpasync16(_sa + 16, pAhi + (size_t)_k * 1024 + abyte / 2 + 8);             \
        uint32_t _sb = sbase + (stage) * AVSTAGE + AVPANA + ar * AV_SB + bbyte;    \
        cpasync16(_sb,          pBhi + (size_t)_k * 512 + bbyte / 2);              \
        cpasync16(_sb + AVPANB, pBlo + (size_t)_k * 512 + bbyte / 2);              \
        CP_COMMIT();                                                               \
    } while (0)

    AV_LOAD_STAGE(0, 0);
    AV_LOAD_STAGE(1, 1);

    const int rAk = (lane & 7) + ((lane >> 4) & 1) * 8;
    const int cAm = ((lane >> 3) & 1) * 8;
    const int rBk = (lane & 7) + ((lane >> 3) & 1) * 8;
    const int cBn = ((lane >> 4) & 1) * 8;

    int cs = 0, ns = 2;
    for (int ko = 0; ko < NK; ko++) {
        if (ko + 1 < NK) { CP_WAIT(1); } else { CP_WAIT(0); }
        __syncthreads();
        if (ko + 2 < NK) { AV_LOAD_STAGE(ns, ko + 2); }

        const uint32_t st  = sbase + cs * AVSTAGE;
        const uint32_t pAh = st;
        const uint32_t pBh = st + AVPANA, pBl = st + AVPANA + AVPANB;

#pragma unroll
        for (int ks = 0; ks < 2; ks++) {
            uint32_t ahi[2][4];
#pragma unroll
            for (int mi = 0; mi < 2; mi++) {
                const uint32_t offA =
                    (uint32_t)((ks * 16 + rAk) * AV_SA + (warpM + mi * 16 + cAm) * 2);
                LDSM4T(ahi[mi][0], ahi[mi][1], ahi[mi][2], ahi[mi][3], pAh + offA);
            }
#pragma unroll
            for (int pr = 0; pr < 4; pr++) {
                uint32_t bh[2][2], bl[2][2];
                const uint32_t offB =
                    (uint32_t)((ks * 16 + rBk) * AV_SB + (warpN + pr * 16 + cBn) * 2);
                LDSM4T(bh[0][0], bh[0][1], bh[1][0], bh[1][1], pBh + offB);
                LDSM4T(bl[0][0], bl[0][1], bl[1][0], bl[1][1], pBl + offB);
#pragma unroll
                for (int mi = 0; mi < 2; mi++)
#pragma unroll
                    for (int nb = 0; nb < 2; nb++) {
                        float* a4 = acc[mi][2 * pr + nb];
                        MMA16816(a4, ahi[mi], bh[nb]);
                        MMA16816(a4, ahi[mi], bl[nb]);
                    }
            }
        }
        cs = cs == 2 ? 0 : cs + 1;
        ns = ns == 2 ? 0 : ns + 1;
    }

    const int gid = lane >> 2, tq = lane & 3;
    const int h = z >> 1, b = z & 1;
    const float g = gamma[h];
    const float inv = 1.0f / (g + 1.0f);
#pragma unroll
    for (int mi = 0; mi < 2; mi++) {
#pragma unroll
        for (int h2 = 0; h2 < 2; h2++) {
            const int m = bm + warpM + mi * 16 + gid + h2 * 8;
#pragma unroll
            for (int nj = 0; nj < 8; nj++) {
                const int n = bn + warpN + nj * 8 + tq * 2;
                float v0 = acc[mi][nj][h2 * 2 + 0];
                float v1 = acc[mi][nj][h2 * 2 + 1];
                const float2 x2 = *reinterpret_cast<const float2*>(
                    g_XP + ((size_t)(b * 1024 + m)) * 512 + n);
                float* dst = out + ((size_t)((b * 8 + h) * 1024 + m)) * 512 + n;
                *reinterpret_cast<float2*>(dst) =
                    make_float2((g * v0 + x2.x) * inv, (g * v1 + x2.y) * inv);
            }
        }
    }
}

// ---------------------------------------------------------------------------
// Launcher
// ---------------------------------------------------------------------------
extern "C" void kernel_launch(void* const* d_in, const int* in_sizes, int n_in,
                              void* d_out, int out_size) {
    using namespace cfg;
    const float* x     = (const float*)d_in[0];
    const float* y     = (const float*)d_in[1];
    const float* Wq    = (const float*)d_in[2];
    const float* bq    = (const float*)d_in[3];
    const float* Wk    = (const float*)d_in[4];
    const float* bk    = (const float*)d_in[5];
    const float* Wv    = (const float*)d_in[6];
    const float* bv    = (const float*)d_in[7];
    const float* Wp    = (const float*)d_in[8];
    const float* gamma = (const float*)d_in[9];
    const unsigned char* mask = (const unsigned char*)d_in[10];
    float* out = (float*)d_out;

    __half *xhi, *xlo, *wqh, *wql, *wkh, *wkl, *wvh, *wvl, *wph, *wpl;
    __half *qhi, *qlo, *khi, *klo, *vhi, *vlo, *ahi, *ylo;
    float *pE, *pXP;
    cudaGetSymbolAddress((void**)&xhi, g_xhi);    cudaGetSymbolAddress((void**)&xlo, g_xlo);
    cudaGetSymbolAddress((void**)&wqh, g_Wqt_hi); cudaGetSymbolAddress((void**)&wql, g_Wqt_lo);
    cudaGetSymbolAddress((void**)&wkh, g_Wkt_hi); cudaGetSymbolAddress((void**)&wkl, g_Wkt_lo);
    cudaGetSymbolAddress((void**)&wvh, g_Wvt_hi); cudaGetSymbolAddress((void**)&wvl, g_Wvt_lo);
    cudaGetSymbolAddress((void**)&wph, g_Wpt_hi); cudaGetSymbolAddress((void**)&wpl, g_Wpt_lo);
    cudaGetSymbolAddress((void**)&qhi, g_Qhi);    cudaGetSymbolAddress((void**)&qlo, g_Qlo);
    cudaGetSymbolAddress((void**)&khi, g_Khi);    cudaGetSymbolAddress((void**)&klo, g_Klo);
    cudaGetSymbolAddress((void**)&vhi, g_Vhi);    cudaGetSymbolAddress((void**)&vlo, g_Vlo);
    cudaGetSymbolAddress((void**)&pE,  g_E);
    cudaGetSymbolAddress((void**)&ahi, g_Ahi);    cudaGetSymbolAddress((void**)&ylo, g_Ylo);
    cudaGetSymbolAddress((void**)&pXP, g_XP);

    cudaFuncSetAttribute(gemm_qkv,    cudaFuncAttributeMaxDynamicSharedMemorySize, KSMEM);
    cudaFuncSetAttribute(gemm_energy, cudaFuncAttributeMaxDynamicSharedMemorySize, KSMEM);
    cudaFuncSetAttribute(gemm_av,     cudaFuncAttributeMaxDynamicSharedMemorySize, AVSMEM);

    decode_mask_kernel<<<1, 1024>>>(mask);

    // x -> xhi/xlo; y -> g_Ahi (hi, temp reuse) / g_Ylo (lo)
    conv_split2_kernel<<<dim3(512, 1, 2), 256>>>(x, y, xhi, xlo, ahi, ylo, 2048 * 512);

    transconv4_kernel<<<dim3(128, 16, 4), dim3(32, 8)>>>(Wq, Wk, Wv, Wp,
                                                         wqh, wql, wkh, wkl,
                                                         wvh, wvl, wph, wpl);

    // Merged Q/K/V/xp projections (V is 2-term; Q/K/xp 3-term)
    gemm_qkv<<<dim3(32, 8, 4), 512, KSMEM>>>(xhi, xlo, ahi, ylo,
                                             wqh, wql, wkh, wkl, wvh, wvl, wph, wpl,
                                             bq, bk, bv,
                                             qhi, qlo, khi, klo, vhi, vlo, pXP);

    // Energy + mask (3-term)
    gemm_energy<<<dim3(8, 4, HB), 512, KSMEM>>>(qhi, qlo, khi, klo, pE);

    // softmax -> attn fp16 (overwrites y-hi scratch)
    softmax_split_kernel<<<HB * SEQ, 256>>>(pE, ahi);

    // AV: attn x (Vhi + Vlo) + blend
    gemm_av<<<dim3(4, 4, HB), 512, AVSMEM>>>(ahi, vhi, vlo, out, gamma);

    (void)in_sizes; (void)n_in; (void)out_size;
}